// round 2
// baseline (speedup 1.0000x reference)
#include <cuda_runtime.h>
#include <math.h>

#define BATCH 8
#define SEQ 1024
#define DMODEL 1024
#define NH 16
#define DKH 64
#define FF 4096
#define ROWS (BATCH*SEQ)

// ---------------- scratch (device globals: allocation-free rule) ----------------
__device__ float g_xn [(size_t)ROWS*DMODEL];
__device__ float g_q  [(size_t)ROWS*DMODEL];   // [B,H,S,DK]
__device__ float g_k  [(size_t)ROWS*DMODEL];   // [B,H,S,DK]
__device__ float g_v  [(size_t)ROWS*DMODEL];   // [B,H,S,DK]
__device__ float g_ctx[(size_t)ROWS*DMODEL];   // [B,S,D]
__device__ float g_x1 [(size_t)ROWS*DMODEL];
__device__ float g_xn2[(size_t)ROWS*DMODEL];
__device__ float g_h1 [(size_t)ROWS*FF];

// ---------------- helpers ----------------
__device__ __forceinline__ unsigned f2tf(float f){
    unsigned r; asm("cvt.rna.tf32.f32 %0, %1;" : "=r"(r) : "f"(f)); return r;
}
__device__ __forceinline__ void mma8(float* d, const unsigned* a, const unsigned* b){
    asm volatile("mma.sync.aligned.m16n8k8.row.col.f32.tf32.tf32.f32 "
        "{%0,%1,%2,%3},{%4,%5,%6,%7},{%8,%9},{%0,%1,%2,%3};\n"
        : "+f"(d[0]), "+f"(d[1]), "+f"(d[2]), "+f"(d[3])
        : "r"(a[0]), "r"(a[1]), "r"(a[2]), "r"(a[3]), "r"(b[0]), "r"(b[1]));
}
__device__ __forceinline__ void fma2(unsigned long long &d, unsigned long long a, unsigned long long b){
    asm("fma.rn.f32x2 %0, %1, %2, %0;" : "+l"(d) : "l"(a), "l"(b));
}
__device__ __forceinline__ unsigned long long mul2(unsigned long long a, unsigned long long b){
    unsigned long long r; asm("mul.rn.f32x2 %0, %1, %2;" : "=l"(r) : "l"(a), "l"(b)); return r;
}
__device__ __forceinline__ unsigned long long pack2(float x, float y){
    unsigned long long r; asm("mov.b64 %0, {%1, %2};" : "=l"(r) : "f"(x), "f"(y)); return r;
}
__device__ __forceinline__ float2 unpack2(unsigned long long v){
    float2 r; asm("mov.b64 {%0, %1}, %2;" : "=f"(r.x), "=f"(r.y) : "l"(v)); return r;
}

// ---------------- LayerNorm: one block per row ----------------
__global__ void __launch_bounds__(256) ln_kernel(const float* __restrict__ x,
        const float* __restrict__ gg, const float* __restrict__ bb, float* __restrict__ y){
    __shared__ float red[8];
    __shared__ float bc;
    int row = blockIdx.x;
    const float4* xr = (const float4*)(x + (size_t)row*DMODEL);
    float4 v = xr[threadIdx.x];
    float s = v.x+v.y+v.z+v.w;
    #pragma unroll
    for (int o=16;o;o>>=1) s += __shfl_xor_sync(0xffffffffu, s, o);
    if ((threadIdx.x&31)==0) red[threadIdx.x>>5] = s;
    __syncthreads();
    if (threadIdx.x==0){ float t=0; for(int i=0;i<8;i++) t+=red[i]; bc = t*(1.0f/DMODEL); }
    __syncthreads();
    float mu = bc;
    float dx0=v.x-mu, dx1=v.y-mu, dx2=v.z-mu, dx3=v.w-mu;
    float q = dx0*dx0+dx1*dx1+dx2*dx2+dx3*dx3;
    #pragma unroll
    for (int o=16;o;o>>=1) q += __shfl_xor_sync(0xffffffffu, q, o);
    if ((threadIdx.x&31)==0) red[threadIdx.x>>5] = q;
    __syncthreads();
    if (threadIdx.x==0){ float t=0; for(int i=0;i<8;i++) t+=red[i]; bc = rsqrtf(t*(1.0f/DMODEL) + 1e-6f); }
    __syncthreads();
    float rs = bc;
    const float4 g4 = ((const float4*)gg)[threadIdx.x];
    const float4 b4 = ((const float4*)bb)[threadIdx.x];
    float4 o;
    o.x = dx0*rs*g4.x + b4.x;
    o.y = dx1*rs*g4.y + b4.y;
    o.z = dx2*rs*g4.z + b4.z;
    o.w = dx3*rs*g4.w + b4.w;
    ((float4*)(y + (size_t)row*DMODEL))[threadIdx.x] = o;
}

// ---------------- TF32 GEMM 128x128x16, 256 threads ----------------
// AMODE: 0 = plain row-major A[M,K]; 1 = implicit im2col conv (CIN = 1<<CSH, kernel width 3, SAME)
// EPI:   0 = scatter to [B,H,S,DK] * scale (QKV)
//        1 = C = res + acc                  (attn out proj + residual)
//        2 = C = relu(acc + bias)           (conv1)
//        3 = C = res + relu(acc + bias)     (conv2 -> final output)
#define BM 128
#define BN 128
#define BK 16
#define ASTRIDE (BK+4)    // 20: bank-conflict-free for A fragment reads
#define BSTRIDE (BN+8)    // 136: bank-conflict-free for B fragment reads

template<int AMODE,int EPI,int CSH>
__global__ void __launch_bounds__(256,2) gemm_tf32(
    const float* __restrict__ A, const float* __restrict__ Bw,
    float* __restrict__ C, const float* __restrict__ bias,
    const float* __restrict__ res, int N, int Kd, float scale)
{
    __shared__ unsigned sA[BM*ASTRIDE];
    __shared__ unsigned sB[BK*BSTRIDE];
    const int tid = threadIdx.x;
    const int bm = blockIdx.y*BM, bn = blockIdx.x*BN;
    const int warp = tid>>5, lane = tid&31;
    const int wm = (warp&3)*32, wn = (warp>>2)*64;
    const int g = lane>>2, tg = lane&3;

    float acc[2][8][4];
    #pragma unroll
    for (int i=0;i<2;i++)
        #pragma unroll
        for (int j=0;j<8;j++)
            #pragma unroll
            for (int e=0;e<4;e++) acc[i][j][e]=0.f;

    for (int k0=0;k0<Kd;k0+=BK){
        #pragma unroll
        for (int i=0;i<2;i++){
            int f = tid + i*256;
            // ---- A tile: 128 x 16 ----
            int row = f>>2, c4 = (f&3)*4;
            float4 val;
            if (AMODE==0){
                val = *(const float4*)(A + (size_t)(bm+row)*Kd + (k0+c4));
            } else {
                int m = bm+row, b = m>>10, s = m&1023;
                int kk = k0 + c4, kw = kk>>CSH, cin = kk & ((1<<CSH)-1);
                int ss = s + kw - 1;
                if ((unsigned)ss < 1024u)
                    val = *(const float4*)(A + (((size_t)(b<<10)+ss)<<CSH) + cin);
                else val = make_float4(0.f,0.f,0.f,0.f);
            }
            *(uint2*)&sA[row*ASTRIDE + c4]     = make_uint2(f2tf(val.x), f2tf(val.y));
            *(uint2*)&sA[row*ASTRIDE + c4 + 2] = make_uint2(f2tf(val.z), f2tf(val.w));
            // ---- B tile: 16 x 128 ----
            int rb = f>>5, cb = (f&31)*4;
            float4 bv = *(const float4*)(Bw + (size_t)(k0+rb)*N + bn + cb);
            *(uint4*)&sB[rb*BSTRIDE + cb] =
                make_uint4(f2tf(bv.x), f2tf(bv.y), f2tf(bv.z), f2tf(bv.w));
        }
        __syncthreads();
        #pragma unroll
        for (int ks=0;ks<2;ks++){
            int kb = ks*8;
            unsigned afr[2][4], bfr[8][2];
            #pragma unroll
            for (int im=0;im<2;im++){
                int m = wm + im*16;
                afr[im][0] = sA[(m+g  )*ASTRIDE + kb + tg];
                afr[im][1] = sA[(m+g+8)*ASTRIDE + kb + tg];
                afr[im][2] = sA[(m+g  )*ASTRIDE + kb + tg + 4];
                afr[im][3] = sA[(m+g+8)*ASTRIDE + kb + tg + 4];
            }
            #pragma unroll
            for (int jn=0;jn<8;jn++){
                int n = wn + jn*8;
                bfr[jn][0] = sB[(kb+tg  )*BSTRIDE + n + g];
                bfr[jn][1] = sB[(kb+tg+4)*BSTRIDE + n + g];
            }
            #pragma unroll
            for (int im=0;im<2;im++)
                #pragma unroll
                for (int jn=0;jn<8;jn++)
                    mma8(acc[im][jn], afr[im], bfr[jn]);
        }
        __syncthreads();
    }
    // ---- epilogue ----
    #pragma unroll
    for (int im=0;im<2;im++){
        #pragma unroll
        for (int jn=0;jn<8;jn++){
            #pragma unroll
            for (int e=0;e<4;e++){
                int row = bm + wm + im*16 + g + ((e>=2)?8:0);
                int col = bn + wn + jn*8 + 2*tg + (e&1);
                float va = acc[im][jn][e];
                if (EPI==0){
                    int b = row>>10, s = row&1023, h = col>>6, dk = col&63;
                    C[((((size_t)((b<<4)+h))<<10) + s)*DKH + dk] = va*scale;
                } else if (EPI==1){
                    size_t idx = (size_t)row*N + col;
                    C[idx] = res[idx] + va;
                } else if (EPI==2){
                    size_t idx = (size_t)row*N + col;
                    C[idx] = fmaxf(va + bias[col], 0.f);
                } else {
                    size_t idx = (size_t)row*N + col;
                    C[idx] = res[idx] + fmaxf(va + bias[col], 0.f);
                }
            }
        }
    }
}

// ---------------- flash attention: 1 thread = 1 query row, packed f32x2 ----------------
#define TQ 128
#define TK 64

__global__ void __launch_bounds__(128) attn_kernel(const int* __restrict__ mask){
    __shared__ unsigned long long sK[TK*32];
    __shared__ unsigned long long sV[TK*32];
    __shared__ int sM[TK];
    const int bh = blockIdx.y;
    const int b = bh >> 4, h = bh & 15;
    const int qi = blockIdx.x*TQ + threadIdx.x;
    const unsigned long long* qp =
        (const unsigned long long*)(g_q + (((size_t)bh<<10) + qi)*DKH);
    unsigned long long q2[32], o2[32];
    #pragma unroll
    for (int i=0;i<32;i++){ q2[i] = qp[i]; o2[i] = 0ull; }
    float mrun = -3.0e38f, lrun = 0.f;
    const float* kbase = g_k + (((size_t)bh)<<10)*DKH;
    const float* vbase = g_v + (((size_t)bh)<<10)*DKH;
    const int* mbase = mask + (b<<10);

    #pragma unroll 1
    for (int kt=0;kt<SEQ/TK;kt++){
        __syncthreads();
        #pragma unroll
        for (int i=0;i<8;i++){
            int f = i*128 + threadIdx.x;
            int r = f>>4, c = f&15;
            *((float4*)&sK[r*32 + c*2]) = ((const float4*)(kbase + (size_t)(kt*TK + r)*DKH))[c];
            *((float4*)&sV[r*32 + c*2]) = ((const float4*)(vbase + (size_t)(kt*TK + r)*DKH))[c];
        }
        if (threadIdx.x < TK) sM[threadIdx.x] = mbase[kt*TK + threadIdx.x];
        __syncthreads();

        #pragma unroll 1
        for (int jg=0;jg<TK/8;jg++){
            float sc[8];
            #pragma unroll
            for (int jj=0;jj<8;jj++){
                const unsigned long long* kr = &sK[(jg*8+jj)*32];
                unsigned long long a = 0ull;
                #pragma unroll
                for (int dd=0;dd<32;dd++) fma2(a, q2[dd], kr[dd]);
                float2 p = unpack2(a);
                float s = p.x + p.y;
                sc[jj] = sM[jg*8+jj] ? -1.0e30f : s;
            }
            float nm = mrun;
            #pragma unroll
            for (int jj=0;jj<8;jj++) nm = fmaxf(nm, sc[jj]);
            float corr = __expf(mrun - nm);
            float p[8]; float psum = 0.f;
            #pragma unroll
            for (int jj=0;jj<8;jj++){ p[jj] = __expf(sc[jj] - nm); psum += p[jj]; }
            lrun = lrun*corr + psum;
            mrun = nm;
            unsigned long long c2 = pack2(corr, corr);
            #pragma unroll
            for (int dd=0;dd<32;dd++) o2[dd] = mul2(o2[dd], c2);
            #pragma unroll
            for (int jj=0;jj<8;jj++){
                unsigned long long p2 = pack2(p[jj], p[jj]);
                const unsigned long long* vr = &sV[(jg*8+jj)*32];
                #pragma unroll
                for (int dd=0;dd<32;dd++) fma2(o2[dd], p2, vr[dd]);
            }
        }
    }
    float inv = 1.f / lrun;
    float2* outp = (float2*)(g_ctx + ((size_t)((b<<10) + qi))*DMODEL + h*DKH);
    #pragma unroll
    for (int dd=0;dd<32;dd++){
        float2 t = unpack2(o2[dd]);
        outp[dd] = make_float2(t.x*inv, t.y*inv);
    }
}

// ---------------- launch ----------------
extern "C" void kernel_launch(void* const* d_in, const int* in_sizes, int n_in,
                              void* d_out, int out_size){
    const float* x    = (const float*)d_in[0];
    const int*   mask = (const int*)  d_in[1];
    const float* Wq   = (const float*)d_in[2];
    const float* Wk   = (const float*)d_in[3];
    const float* Wv   = (const float*)d_in[4];
    const float* Wo   = (const float*)d_in[5];
    const float* ln1g = (const float*)d_in[6];
    const float* ln1b = (const float*)d_in[7];
    const float* ln2g = (const float*)d_in[8];
    const float* ln2b = (const float*)d_in[9];
    const float* c1w  = (const float*)d_in[10];
    const float* c1b  = (const float*)d_in[11];
    const float* c2w  = (const float*)d_in[12];
    const float* c2b  = (const float*)d_in[13];
    float* out = (float*)d_out;

    float *xn, *q, *k, *v, *ctx, *x1, *xn2, *h1;
    cudaGetSymbolAddress((void**)&xn,  g_xn);
    cudaGetSymbolAddress((void**)&q,   g_q);
    cudaGetSymbolAddress((void**)&k,   g_k);
    cudaGetSymbolAddress((void**)&v,   g_v);
    cudaGetSymbolAddress((void**)&ctx, g_ctx);
    cudaGetSymbolAddress((void**)&x1,  g_x1);
    cudaGetSymbolAddress((void**)&xn2, g_xn2);
    cudaGetSymbolAddress((void**)&h1,  g_h1);

    // 1) LN1
    ln_kernel<<<ROWS,256>>>(x, ln1g, ln1b, xn);

    // 2) QKV projections (scatter into [B,H,S,DK]; q pre-scaled by 1/sqrt(DK))
    dim3 gqkv(DMODEL/BN, ROWS/BM);
    gemm_tf32<0,0,0><<<gqkv,256>>>(xn, Wq, q, nullptr, nullptr, DMODEL, DMODEL, 0.125f);
    gemm_tf32<0,0,0><<<gqkv,256>>>(xn, Wk, k, nullptr, nullptr, DMODEL, DMODEL, 1.0f);
    gemm_tf32<0,0,0><<<gqkv,256>>>(xn, Wv, v, nullptr, nullptr, DMODEL, DMODEL, 1.0f);

    // 3) attention (flash, online softmax, key mask)
    dim3 ga(SEQ/TQ, BATCH*NH);
    attn_kernel<<<ga,128>>>(mask);

    // 4) output projection + residual
    gemm_tf32<0,1,0><<<gqkv,256>>>(ctx, Wo, x1, nullptr, x, DMODEL, DMODEL, 1.0f);

    // 5) LN2
    ln_kernel<<<ROWS,256>>>(x1, ln2g, ln2b, xn2);

    // 6) conv1 (implicit im2col K=3, CIN=1024) + bias + ReLU
    dim3 g1(FF/BN, ROWS/BM);
    gemm_tf32<1,2,10><<<g1,256>>>(xn2, c1w, h1, c1b, nullptr, FF, 3*DMODEL, 1.0f);

    // 7) conv2 (CIN=4096) + bias + ReLU + residual -> final output
    dim3 g2(DMODEL/BN, ROWS/BM);
    gemm_tf32<1,3,12><<<g2,256>>>(h1, c2w, out, c2b, x1, DMODEL, 3*FF, 1.0f);
}

// round 8
// speedup vs baseline: 1.6618x; 1.6618x over previous
#include <cuda_runtime.h>
#include <math.h>
#include <stdint.h>

#define BATCH 8
#define SEQ 1024
#define DMODEL 1024
#define NH 16
#define DKH 64
#define FF 4096
#define ROWS (BATCH*SEQ)

// ---------------- scratch (device globals: allocation-free rule) ----------------
__device__ float g_xn [(size_t)ROWS*DMODEL];
__device__ float g_q  [(size_t)ROWS*DMODEL];   // [B,H,S,DK]
__device__ float g_k  [(size_t)ROWS*DMODEL];   // [B,H,S,DK]
__device__ float g_v  [(size_t)ROWS*DMODEL];   // [B,H,S,DK]
__device__ float g_ctx[(size_t)ROWS*DMODEL];   // [B,S,D]
__device__ float g_x1 [(size_t)ROWS*DMODEL];
__device__ float g_xn2[(size_t)ROWS*DMODEL];
__device__ float g_h1 [(size_t)ROWS*FF];
// tf32-prerounded weights
__device__ float g_wqkv[(size_t)DMODEL*3*DMODEL];   // [K=1024, N=3072] packed q|k|v
__device__ float g_wo  [(size_t)DMODEL*DMODEL];     // [K,N]
__device__ float g_c1  [(size_t)3*DMODEL*FF];       // [K=3072, N=4096]
__device__ float g_c2  [(size_t)3*FF*DMODEL];       // [K=12288, N=1024]

// ---------------- helpers ----------------
__device__ __forceinline__ float tf32r(float f){
    unsigned u; asm("cvt.rna.tf32.f32 %0, %1;" : "=r"(u) : "f"(f));
    return __uint_as_float(u);
}
__device__ __forceinline__ uint32_t smem_u32(const void* p){
    uint32_t a;
    asm("{ .reg .u64 t; cvta.to.shared.u64 t, %1; cvt.u32.u64 %0, t; }" : "=r"(a) : "l"(p));
    return a;
}
__device__ __forceinline__ void mma8(float* d, const unsigned* a, const unsigned* b){
    asm volatile("mma.sync.aligned.m16n8k8.row.col.f32.tf32.tf32.f32 "
        "{%0,%1,%2,%3},{%4,%5,%6,%7},{%8,%9},{%0,%1,%2,%3};\n"
        : "+f"(d[0]), "+f"(d[1]), "+f"(d[2]), "+f"(d[3])
        : "r"(a[0]), "r"(a[1]), "r"(a[2]), "r"(a[3]), "r"(b[0]), "r"(b[1]));
}
// packed f32x2 helpers (attention)
__device__ __forceinline__ void fma2(unsigned long long &d, unsigned long long a, unsigned long long b){
    asm("fma.rn.f32x2 %0, %1, %2, %0;" : "+l"(d) : "l"(a), "l"(b));
}
__device__ __forceinline__ unsigned long long mul2(unsigned long long a, unsigned long long b){
    unsigned long long r; asm("mul.rn.f32x2 %0, %1, %2;" : "=l"(r) : "l"(a), "l"(b)); return r;
}
__device__ __forceinline__ unsigned long long pack2(float x, float y){
    unsigned long long r; asm("mov.b64 %0, {%1, %2};" : "=l"(r) : "f"(x), "f"(y)); return r;
}
__device__ __forceinline__ float2 unpack2(unsigned long long v){
    float2 r; asm("mov.b64 {%0, %1}, %2;" : "=f"(r.x), "=f"(r.y) : "l"(v)); return r;
}

// ---------------- weight preprocessing ----------------
// plain tf32 round-copy (float4 grid-stride)
__global__ void __launch_bounds__(256) round_copy(const float4* __restrict__ in,
        float4* __restrict__ out, int n4){
    int i = blockIdx.x*256 + threadIdx.x;
    if (i < n4){
        float4 v = in[i];
        v.x = tf32r(v.x); v.y = tf32r(v.y); v.z = tf32r(v.z); v.w = tf32r(v.w);
        out[i] = v;
    }
}
// pack W[1024,1024] into dst[k*3072 + off + n], tf32-rounded
__global__ void __launch_bounds__(256) pack_w(const float4* __restrict__ in,
        float4* __restrict__ out, int off4){
    int i = blockIdx.x*256 + threadIdx.x;   // over 1024*256 float4s
    int kk = i >> 8, n4 = i & 255;
    float4 v = in[i];
    v.x = tf32r(v.x); v.y = tf32r(v.y); v.z = tf32r(v.z); v.w = tf32r(v.w);
    out[kk*768 + off4 + n4] = v;
}

// ---------------- LayerNorm (output rounded to tf32 for GEMM input) ----------------
__global__ void __launch_bounds__(256) ln_kernel(const float* __restrict__ x,
        const float* __restrict__ gg, const float* __restrict__ bb, float* __restrict__ y){
    __shared__ float red[8];
    __shared__ float bc;
    int row = blockIdx.x;
    const float4* xr = (const float4*)(x + (size_t)row*DMODEL);
    float4 v = xr[threadIdx.x];
    float s = v.x+v.y+v.z+v.w;
    #pragma unroll
    for (int o=16;o;o>>=1) s += __shfl_xor_sync(0xffffffffu, s, o);
    if ((threadIdx.x&31)==0) red[threadIdx.x>>5] = s;
    __syncthreads();
    if (threadIdx.x==0){ float t=0; for(int i=0;i<8;i++) t+=red[i]; bc = t*(1.0f/DMODEL); }
    __syncthreads();
    float mu = bc;
    float dx0=v.x-mu, dx1=v.y-mu, dx2=v.z-mu, dx3=v.w-mu;
    float q = dx0*dx0+dx1*dx1+dx2*dx2+dx3*dx3;
    #pragma unroll
    for (int o=16;o;o>>=1) q += __shfl_xor_sync(0xffffffffu, q, o);
    if ((threadIdx.x&31)==0) red[threadIdx.x>>5] = q;
    __syncthreads();
    if (threadIdx.x==0){ float t=0; for(int i=0;i<8;i++) t+=red[i]; bc = rsqrtf(t*(1.0f/DMODEL) + 1e-6f); }
    __syncthreads();
    float rs = bc;
    const float4 g4 = ((const float4*)gg)[threadIdx.x];
    const float4 b4 = ((const float4*)bb)[threadIdx.x];
    float4 o;
    o.x = tf32r(dx0*rs*g4.x + b4.x);
    o.y = tf32r(dx1*rs*g4.y + b4.y);
    o.z = tf32r(dx2*rs*g4.z + b4.z);
    o.w = tf32r(dx3*rs*g4.w + b4.w);
    ((float4*)(y + (size_t)row*DMODEL))[threadIdx.x] = o;
}

// ---------------- pipelined TF32 mma.sync GEMM: 128x128 tile, BK=32, 3-stage cp.async ----
// A[M,K] row-major (tf32-prerounded), B[K,N] row-major (tf32-prerounded)
// AMODE: 0 = plain; 1 = implicit im2col conv (CIN=1<<CSH, width 3, SAME)
// EPI:   0 = qkv scatter [B,H,S,DK] (q scaled)   1 = res+acc
//        2 = round(relu(acc+bias))               3 = res+relu(acc+bias)
#define BM 128
#define BN 128
#define BK 32
#define ASTRIDE 36            // 32+4: conflict-free (4g+tg distinct)
#define BSTRIDE 132           // 128+4: conflict-free (132%32=4 -> 4tg+g distinct)
#define ABYTES (BM*ASTRIDE*4)         // 18432
#define BBYTES (BK*BSTRIDE*4)         // 16896
#define STAGEB (ABYTES+BBYTES)        // 35328
#define NSTAGE 3
#define SMEM_GEMM (NSTAGE*STAGEB)     // 105984

template<int AMODE,int CSH>
__device__ __forceinline__ void load_chunk(const float* __restrict__ A,
        const float* __restrict__ Bw, int Kd, int N, int bm, int bn, int c,
        uint32_t smem_base, int tid){
    const int k0 = c*BK;
    const uint32_t st = smem_base + (uint32_t)(c % NSTAGE)*STAGEB;
    // A tile: 128 rows x 32 floats = 1024 float4s, 4 per thread
    #pragma unroll
    for (int i=0;i<4;i++){
        int idx = i*256 + tid;
        int row = idx>>3, seg = idx&7;
        uint32_t so = st + (uint32_t)(row*ASTRIDE + seg*4)*4u;
        const float* src; int sz = 16;
        if (AMODE==0){
            src = A + (size_t)(bm+row)*Kd + k0 + seg*4;
        } else {
            int m = bm+row, b = m>>10, s = m&1023;
            int kw = k0 >> CSH;
            int cin = (k0 & ((1<<CSH)-1)) + seg*4;
            int ss = s + kw - 1;
            src = A + (((size_t)((b<<10)+ss)) << CSH) + cin;
            if ((unsigned)ss >= 1024u) sz = 0;
        }
        asm volatile("cp.async.cg.shared.global [%0], [%1], 16, %2;"
                     :: "r"(so), "l"(src), "r"(sz));
    }
    // B tile: 32 rows x 128 floats = 1024 float4s
    #pragma unroll
    for (int i=0;i<4;i++){
        int idx = i*256 + tid;
        int kk = idx>>5, n4 = idx&31;
        uint32_t so = st + (uint32_t)ABYTES + (uint32_t)(kk*BSTRIDE + n4*4)*4u;
        const float* src = Bw + (size_t)(k0+kk)*N + bn + n4*4;
        asm volatile("cp.async.cg.shared.global [%0], [%1], 16, %2;"
                     :: "r"(so), "l"(src), "r"(16));
    }
    asm volatile("cp.async.commit_group;" ::: "memory");
}

template<int AMODE,int EPI,int CSH>
__global__ void __launch_bounds__(256,2)
gemm_p(const float* __restrict__ A, const float* __restrict__ Bw,
       float* __restrict__ C, const float* __restrict__ bias,
       const float* __restrict__ res, int Kd, int N, float scale,
       float* __restrict__ Kp, float* __restrict__ Vp)
{
    extern __shared__ __align__(16) char smem[];
    uint32_t smem_base = smem_u32(smem);
    const int tid = threadIdx.x;
    const int bm = blockIdx.y*BM, bn = blockIdx.x*BN;
    const int warp = tid>>5, lane = tid&31;
    const int wm = (warp&3)*32, wn = (warp>>2)*64;
    const int g = lane>>2, tg = lane&3;
    const int NC = Kd/BK;

    float acc[2][8][4];
    #pragma unroll
    for (int i=0;i<2;i++)
        #pragma unroll
        for (int j=0;j<8;j++)
            #pragma unroll
            for (int e=0;e<4;e++) acc[i][j][e]=0.f;

    load_chunk<AMODE,CSH>(A,Bw,Kd,N,bm,bn,0,smem_base,tid);
    load_chunk<AMODE,CSH>(A,Bw,Kd,N,bm,bn,1,smem_base,tid);

    for (int c=0;c<NC;c++){
        if (c+2 < NC){
            load_chunk<AMODE,CSH>(A,Bw,Kd,N,bm,bn,c+2,smem_base,tid);
            asm volatile("cp.async.wait_group 2;" ::: "memory");
        } else if (c+1 < NC){
            asm volatile("cp.async.wait_group 1;" ::: "memory");
        } else {
            asm volatile("cp.async.wait_group 0;" ::: "memory");
        }
        __syncthreads();
        const unsigned* sA = (const unsigned*)(smem + (size_t)(c%NSTAGE)*STAGEB);
        const unsigned* sB = (const unsigned*)(smem + (size_t)(c%NSTAGE)*STAGEB + ABYTES);
        #pragma unroll
        for (int ks=0;ks<4;ks++){
            int kb = ks*8;
            unsigned afr[2][4], bfr[8][2];
            #pragma unroll
            for (int im=0;im<2;im++){
                int m = wm + im*16;
                afr[im][0] = sA[(m+g  )*ASTRIDE + kb + tg];
                afr[im][1] = sA[(m+g+8)*ASTRIDE + kb + tg];
                afr[im][2] = sA[(m+g  )*ASTRIDE + kb + tg + 4];
                afr[im][3] = sA[(m+g+8)*ASTRIDE + kb + tg + 4];
            }
            #pragma unroll
            for (int jn=0;jn<8;jn++){
                int n = wn + jn*8;
                bfr[jn][0] = sB[(kb+tg  )*BSTRIDE + n + g];
                bfr[jn][1] = sB[(kb+tg+4)*BSTRIDE + n + g];
            }
            #pragma unroll
            for (int im=0;im<2;im++)
                #pragma unroll
                for (int jn=0;jn<8;jn++)
                    mma8(acc[im][jn], afr[im], bfr[jn]);
        }
        __syncthreads();
    }

    // ---- epilogue (float2 stores; e-pairs are column-contiguous) ----
    if (EPI==0){
        const int which = bn >> 10;                 // 0=q 1=k 2=v (uniform per CTA)
        float* dst = (which==0) ? C : (which==1 ? Kp : Vp);
        const float sc = (which==0) ? scale : 1.0f;
        #pragma unroll
        for (int im=0;im<2;im++){
            #pragma unroll
            for (int eh=0;eh<2;eh++){
                int row = bm + wm + im*16 + g + eh*8;
                int b = row>>10, s = row&1023;
                #pragma unroll
                for (int jn=0;jn<8;jn++){
                    int col = (bn & 1023) + wn + jn*8 + 2*tg;
                    int h = col>>6, dk = col&63;
                    float2 o;
                    o.x = acc[im][jn][eh*2  ]*sc;
                    o.y = acc[im][jn][eh*2+1]*sc;
                    *(float2*)(dst + (((size_t)((b<<4)+h)<<10) + s)*DKH + dk) = o;
                }
            }
        }
    } else {
        #pragma unroll
        for (int im=0;im<2;im++){
            #pragma unroll
            for (int eh=0;eh<2;eh++){
                int row = bm + wm + im*16 + g + eh*8;
                #pragma unroll
                for (int jn=0;jn<8;jn++){
                    int col = bn + wn + jn*8 + 2*tg;
                    size_t idx = (size_t)row*N + col;
                    float2 o;
                    o.x = acc[im][jn][eh*2  ];
                    o.y = acc[im][jn][eh*2+1];
                    if (EPI>=2){
                        o.x = fmaxf(o.x + __ldg(bias+col  ), 0.f);
                        o.y = fmaxf(o.y + __ldg(bias+col+1), 0.f);
                    }
                    if (EPI==2){ o.x = tf32r(o.x); o.y = tf32r(o.y); }
                    if (EPI==1 || EPI==3){
                        float2 rv = *(const float2*)(res + idx);
                        o.x += rv.x; o.y += rv.y;
                    }
                    *(float2*)(C + idx) = o;
                }
            }
        }
    }
}

// ---------------- flash attention: 1 thread = 1 query row, packed f32x2 ----------------
#define TQ 128
#define TK 64

__global__ void __launch_bounds__(128) attn_kernel(const int* __restrict__ mask){
    __shared__ unsigned long long sK[TK*32];
    __shared__ unsigned long long sV[TK*32];
    __shared__ int sM[TK];
    const int bh = blockIdx.y;
    const int b = bh >> 4, h = bh & 15;
    const int qi = blockIdx.x*TQ + threadIdx.x;
    const unsigned long long* qp =
        (const unsigned long long*)(g_q + (((size_t)bh<<10) + qi)*DKH);
    unsigned long long q2[32], o2[32];
    #pragma unroll
    for (int i=0;i<32;i++){ q2[i] = qp[i]; o2[i] = 0ull; }
    float mrun = -3.0e38f, lrun = 0.f;
    const float* kbase = g_k + (((size_t)bh)<<10)*DKH;
    const float* vbase = g_v + (((size_t)bh)<<10)*DKH;
    const int* mbase = mask + (b<<10);

    #pragma unroll 1
    for (int kt=0;kt<SEQ/TK;kt++){
        __syncthreads();
        #pragma unroll
        for (int i=0;i<8;i++){
            int f = i*128 + threadIdx.x;
            int r = f>>4, c = f&15;
            *((float4*)&sK[r*32 + c*2]) = ((const float4*)(kbase + (size_t)(kt*TK + r)*DKH))[c];
            *((float4*)&sV[r*32 + c*2]) = ((const float4*)(vbase + (size_t)(kt*TK + r)*DKH))[c];
        }
        if (threadIdx.x < TK) sM[threadIdx.x] = mbase[kt*TK + threadIdx.x];
        __syncthreads();

        #pragma unroll 1
        for (int jg=0;jg<TK/8;jg++){
            float sc[8];
            #pragma unroll
            for (int jj=0;jj<8;jj++){
                const unsigned long long* kr = &sK[(jg*8+jj)*32];
                unsigned long long a = 0ull;
                #pragma unroll
                for (int dd=0;dd<32;dd++) fma2(a, q2[dd], kr[dd]);
                float2 p = unpack2(a);
                float s = p.x + p.y;
                sc[jj] = sM[jg*8+jj] ? -1.0e30f : s;
            }
            float nm = mrun;
            #pragma unroll
            for (int jj=0;jj<8;jj++) nm = fmaxf(nm, sc[jj]);
            float corr = __expf(mrun - nm);
            float p[8]; float psum = 0.f;
            #pragma unroll
            for (int jj=0;jj<8;jj++){ p[jj] = __expf(sc[jj] - nm); psum += p[jj]; }
            lrun = lrun*corr + psum;
            mrun = nm;
            unsigned long long c2 = pack2(corr, corr);
            #pragma unroll
            for (int dd=0;dd<32;dd++) o2[dd] = mul2(o2[dd], c2);
            #pragma unroll
            for (int jj=0;jj<8;jj++){
                unsigned long long p2 = pack2(p[jj], p[jj]);
                const unsigned long long* vr = &sV[(jg*8+jj)*32];
                #pragma unroll
                for (int dd=0;dd<32;dd++) fma2(o2[dd], p2, vr[dd]);
            }
        }
    }
    float inv = 1.f / lrun;
    float2* outp = (float2*)(g_ctx + ((size_t)((b<<10) + qi))*DMODEL + h*DKH);
    #pragma unroll
    for (int dd=0;dd<32;dd++){
        float2 t = unpack2(o2[dd]);
        outp[dd] = make_float2(tf32r(t.x*inv), tf32r(t.y*inv));  // ctx feeds Wo GEMM
    }
}

// ---------------- launch ----------------
extern "C" void kernel_launch(void* const* d_in, const int* in_sizes, int n_in,
                              void* d_out, int out_size){
    const float* x    = (const float*)d_in[0];
    const int*   mask = (const int*)  d_in[1];
    const float* Wq   = (const float*)d_in[2];
    const float* Wk   = (const float*)d_in[3];
    const float* Wv   = (const float*)d_in[4];
    const float* Wo   = (const float*)d_in[5];
    const float* ln1g = (const float*)d_in[6];
    const float* ln1b = (const float*)d_in[7];
    const float* ln2g = (const float*)d_in[8];
    const float* ln2b = (const float*)d_in[9];
    const float* c1w  = (const float*)d_in[10];
    const float* c1b  = (const float*)d_in[11];
    const float* c2w  = (const float*)d_in[12];
    const float* c2b  = (const float*)d_in[13];
    float* out = (float*)d_out;

    float *xn, *q, *k, *v, *ctx, *x1, *xn2, *h1;
    float *wqkv, *wo, *c1, *c2;
    cudaGetSymbolAddress((void**)&xn,  g_xn);
    cudaGetSymbolAddress((void**)&q,   g_q);
    cudaGetSymbolAddress((void**)&k,   g_k);
    cudaGetSymbolAddress((void**)&v,   g_v);
    cudaGetSymbolAddress((void**)&ctx, g_ctx);
    cudaGetSymbolAddress((void**)&x1,  g_x1);
    cudaGetSymbolAddress((void**)&xn2, g_xn2);
    cudaGetSymbolAddress((void**)&h1,  g_h1);
    cudaGetSymbolAddress((void**)&wqkv,g_wqkv);
    cudaGetSymbolAddress((void**)&wo,  g_wo);
    cudaGetSymbolAddress((void**)&c1,  g_c1);
    cudaGetSymbolAddress((void**)&c2,  g_c2);

    cudaFuncSetAttribute(gemm_p<0,0,0>,  cudaFuncAttributeMaxDynamicSharedMemorySize, SMEM_GEMM);
    cudaFuncSetAttribute(gemm_p<0,1,0>,  cudaFuncAttributeMaxDynamicSharedMemorySize, SMEM_GEMM);
    cudaFuncSetAttribute(gemm_p<1,2,10>, cudaFuncAttributeMaxDynamicSharedMemorySize, SMEM_GEMM);
    cudaFuncSetAttribute(gemm_p<1,3,12>, cudaFuncAttributeMaxDynamicSharedMemorySize, SMEM_GEMM);

    // 0) weight prep: tf32 round (+ qkv pack)
    pack_w<<<1024, 256>>>((const float4*)Wq, (float4*)wqkv, 0);
    pack_w<<<1024, 256>>>((const float4*)Wk, (float4*)wqkv, 256);
    pack_w<<<1024, 256>>>((const float4*)Wv, (float4*)wqkv, 512);
    round_copy<<<1024, 256>>>((const float4*)Wo, (float4*)wo, DMODEL*DMODEL/4);
    round_copy<<<(3*DMODEL*FF/4 + 255)/256, 256>>>((const float4*)c1w, (float4*)c1, 3*DMODEL*FF/4);
    round_copy<<<(3*FF*DMODEL/4 + 255)/256, 256>>>((const float4*)c2w, (float4*)c2, 3*FF*DMODEL/4);

    // 1) LN1
    ln_kernel<<<ROWS,256>>>(x, ln1g, ln1b, xn);

    // 2) fused QKV projection: [8192,1024] x [1024,3072], scatter to [B,H,S,DK]
    dim3 gqkv(3*DMODEL/BN, ROWS/BM);   // (24, 64)
    gemm_p<0,0,0><<<gqkv,256,SMEM_GEMM>>>(xn, wqkv, q, nullptr, nullptr,
                                          DMODEL, 3*DMODEL, 0.125f, k, v);

    // 3) attention
    dim3 ga(SEQ/TQ, BATCH*NH);
    attn_kernel<<<ga,128>>>(mask);

    // 4) output projection + residual
    dim3 go(DMODEL/BN, ROWS/BM);
    gemm_p<0,1,0><<<go,256,SMEM_GEMM>>>(ctx, wo, x1, nullptr, x,
                                        DMODEL, DMODEL, 1.0f, nullptr, nullptr);

    // 5) LN2
    ln_kernel<<<ROWS,256>>>(x1, ln2g, ln2b, xn2);

    // 6) conv1 (implicit im2col K=3, CIN=1024) + bias + ReLU (tf32-rounded out)
    gemm_p<1,2,10><<<dim3(FF/BN, ROWS/BM),256,SMEM_GEMM>>>(xn2, c1, h1, c1b, nullptr,
                                        3*DMODEL, FF, 1.0f, nullptr, nullptr);

    // 7) conv2 (CIN=4096) + bias + ReLU + residual -> final output
    gemm_p<1,3,12><<<dim3(DMODEL/BN, ROWS/BM),256,SMEM_GEMM>>>(h1, c2, out, c2b, x1,
                                        3*FF, DMODEL, 1.0f, nullptr, nullptr);
}

// round 9
// speedup vs baseline: 2.0678x; 1.2443x over previous
#include <cuda_runtime.h>
#include <math.h>
#include <stdint.h>

#define BATCH 8
#define SEQ 1024
#define DMODEL 1024
#define NH 16
#define DKH 64
#define FF 4096
#define ROWS (BATCH*SEQ)

// ---------------- scratch (device globals: allocation-free rule) ----------------
__device__ float g_xn [(size_t)ROWS*DMODEL];
__device__ float g_q  [(size_t)ROWS*DMODEL];   // [B,H,S,DK]
__device__ float g_k  [(size_t)ROWS*DMODEL];   // [B,H,S,DK]
__device__ float g_v  [(size_t)ROWS*DMODEL];   // [B,H,S,DK]
__device__ float g_ctx[(size_t)ROWS*DMODEL];   // [B,S,D]
__device__ float g_x1 [(size_t)ROWS*DMODEL];
__device__ float g_xn2[(size_t)ROWS*DMODEL];
__device__ float g_h1 [(size_t)ROWS*FF];
// tf32-prerounded weights
__device__ float g_wqkv[(size_t)DMODEL*3*DMODEL];   // [K=1024, N=3072] packed q|k|v
__device__ float g_wo  [(size_t)DMODEL*DMODEL];     // [K,N]
__device__ float g_c1  [(size_t)3*DMODEL*FF];       // [K=3072, N=4096]
__device__ float g_c2  [(size_t)3*FF*DMODEL];       // [K=12288, N=1024]

// ---------------- helpers ----------------
__device__ __forceinline__ float tf32r(float f){
    unsigned u; asm("cvt.rna.tf32.f32 %0, %1;" : "=r"(u) : "f"(f));
    return __uint_as_float(u);
}
__device__ __forceinline__ uint32_t smem_u32(const void* p){
    uint32_t a;
    asm("{ .reg .u64 t; cvta.to.shared.u64 t, %1; cvt.u32.u64 %0, t; }" : "=r"(a) : "l"(p));
    return a;
}
__device__ __forceinline__ void mma8(float* d, const unsigned* a, const unsigned* b){
    asm volatile("mma.sync.aligned.m16n8k8.row.col.f32.tf32.tf32.f32 "
        "{%0,%1,%2,%3},{%4,%5,%6,%7},{%8,%9},{%0,%1,%2,%3};\n"
        : "+f"(d[0]), "+f"(d[1]), "+f"(d[2]), "+f"(d[3])
        : "r"(a[0]), "r"(a[1]), "r"(a[2]), "r"(a[3]), "r"(b[0]), "r"(b[1]));
}
__device__ __forceinline__ void cpa16(uint32_t so, const float* src){
    asm volatile("cp.async.cg.shared.global [%0], [%1], 16, %2;"
                 :: "r"(so), "l"(src), "r"(16));
}

// ---------------- weight preprocessing ----------------
__global__ void __launch_bounds__(256) round_copy(const float4* __restrict__ in,
        float4* __restrict__ out, int n4){
    int i = blockIdx.x*256 + threadIdx.x;
    if (i < n4){
        float4 v = in[i];
        v.x = tf32r(v.x); v.y = tf32r(v.y); v.z = tf32r(v.z); v.w = tf32r(v.w);
        out[i] = v;
    }
}
__global__ void __launch_bounds__(256) pack_w(const float4* __restrict__ in,
        float4* __restrict__ out, int off4){
    int i = blockIdx.x*256 + threadIdx.x;
    int kk = i >> 8, n4 = i & 255;
    float4 v = in[i];
    v.x = tf32r(v.x); v.y = tf32r(v.y); v.z = tf32r(v.z); v.w = tf32r(v.w);
    out[kk*768 + off4 + n4] = v;
}

// ---------------- LayerNorm ----------------
__global__ void __launch_bounds__(256) ln_kernel(const float* __restrict__ x,
        const float* __restrict__ gg, const float* __restrict__ bb, float* __restrict__ y){
    __shared__ float red[8];
    __shared__ float bc;
    int row = blockIdx.x;
    const float4* xr = (const float4*)(x + (size_t)row*DMODEL);
    float4 v = xr[threadIdx.x];
    float s = v.x+v.y+v.z+v.w;
    #pragma unroll
    for (int o=16;o;o>>=1) s += __shfl_xor_sync(0xffffffffu, s, o);
    if ((threadIdx.x&31)==0) red[threadIdx.x>>5] = s;
    __syncthreads();
    if (threadIdx.x==0){ float t=0; for(int i=0;i<8;i++) t+=red[i]; bc = t*(1.0f/DMODEL); }
    __syncthreads();
    float mu = bc;
    float dx0=v.x-mu, dx1=v.y-mu, dx2=v.z-mu, dx3=v.w-mu;
    float q = dx0*dx0+dx1*dx1+dx2*dx2+dx3*dx3;
    #pragma unroll
    for (int o=16;o;o>>=1) q += __shfl_xor_sync(0xffffffffu, q, o);
    if ((threadIdx.x&31)==0) red[threadIdx.x>>5] = q;
    __syncthreads();
    if (threadIdx.x==0){ float t=0; for(int i=0;i<8;i++) t+=red[i]; bc = rsqrtf(t*(1.0f/DMODEL) + 1e-6f); }
    __syncthreads();
    float rs = bc;
    const float4 g4 = ((const float4*)gg)[threadIdx.x];
    const float4 b4 = ((const float4*)bb)[threadIdx.x];
    float4 o;
    o.x = tf32r(dx0*rs*g4.x + b4.x);
    o.y = tf32r(dx1*rs*g4.y + b4.y);
    o.z = tf32r(dx2*rs*g4.z + b4.z);
    o.w = tf32r(dx3*rs*g4.w + b4.w);
    ((float4*)(y + (size_t)row*DMODEL))[threadIdx.x] = o;
}

// ---------------- pipelined TF32 mma.sync GEMM: 128x128, BK=32, 3-stage ----------------
#define BM 128
#define BN 128
#define BK 32
#define ASTRIDE 36
#define BSTRIDE 132
#define ABYTES (BM*ASTRIDE*4)
#define BBYTES (BK*BSTRIDE*4)
#define STAGEB (ABYTES+BBYTES)
#define NSTAGE 3
#define SMEM_GEMM (NSTAGE*STAGEB)

template<int AMODE,int CSH>
__device__ __forceinline__ void load_chunk(const float* __restrict__ A,
        const float* __restrict__ Bw, int Kd, int N, int bm, int bn, int c,
        uint32_t smem_base, int tid){
    const int k0 = c*BK;
    const uint32_t st = smem_base + (uint32_t)(c % NSTAGE)*STAGEB;
    #pragma unroll
    for (int i=0;i<4;i++){
        int idx = i*256 + tid;
        int row = idx>>3, seg = idx&7;
        uint32_t so = st + (uint32_t)(row*ASTRIDE + seg*4)*4u;
        const float* src; int sz = 16;
        if (AMODE==0){
            src = A + (size_t)(bm+row)*Kd + k0 + seg*4;
        } else {
            int m = bm+row, b = m>>10, s = m&1023;
            int kw = k0 >> CSH;
            int cin = (k0 & ((1<<CSH)-1)) + seg*4;
            int ss = s + kw - 1;
            src = A + (((size_t)((b<<10)+ss)) << CSH) + cin;
            if ((unsigned)ss >= 1024u) sz = 0;
        }
        asm volatile("cp.async.cg.shared.global [%0], [%1], 16, %2;"
                     :: "r"(so), "l"(src), "r"(sz));
    }
    #pragma unroll
    for (int i=0;i<4;i++){
        int idx = i*256 + tid;
        int kk = idx>>5, n4 = idx&31;
        uint32_t so = st + (uint32_t)ABYTES + (uint32_t)(kk*BSTRIDE + n4*4)*4u;
        const float* src = Bw + (size_t)(k0+kk)*N + bn + n4*4;
        asm volatile("cp.async.cg.shared.global [%0], [%1], 16, %2;"
                     :: "r"(so), "l"(src), "r"(16));
    }
    asm volatile("cp.async.commit_group;" ::: "memory");
}

template<int AMODE,int EPI,int CSH>
__global__ void __launch_bounds__(256,2)
gemm_p(const float* __restrict__ A, const float* __restrict__ Bw,
       float* __restrict__ C, const float* __restrict__ bias,
       const float* __restrict__ res, int Kd, int N, float scale,
       float* __restrict__ Kp, float* __restrict__ Vp)
{
    extern __shared__ __align__(16) char smem[];
    uint32_t smem_base = smem_u32(smem);
    const int tid = threadIdx.x;
    const int bm = blockIdx.y*BM, bn = blockIdx.x*BN;
    const int warp = tid>>5, lane = tid&31;
    const int wm = (warp&3)*32, wn = (warp>>2)*64;
    const int g = lane>>2, tg = lane&3;
    const int NC = Kd/BK;

    float acc[2][8][4];
    #pragma unroll
    for (int i=0;i<2;i++)
        #pragma unroll
        for (int j=0;j<8;j++)
            #pragma unroll
            for (int e=0;e<4;e++) acc[i][j][e]=0.f;

    load_chunk<AMODE,CSH>(A,Bw,Kd,N,bm,bn,0,smem_base,tid);
    load_chunk<AMODE,CSH>(A,Bw,Kd,N,bm,bn,1,smem_base,tid);

    for (int c=0;c<NC;c++){
        if (c < NC-1){ asm volatile("cp.async.wait_group 1;" ::: "memory"); }
        else         { asm volatile("cp.async.wait_group 0;" ::: "memory"); }
        __syncthreads();
        if (c+2 < NC) load_chunk<AMODE,CSH>(A,Bw,Kd,N,bm,bn,c+2,smem_base,tid);
        const unsigned* sA = (const unsigned*)(smem + (size_t)(c%NSTAGE)*STAGEB);
        const unsigned* sB = (const unsigned*)(smem + (size_t)(c%NSTAGE)*STAGEB + ABYTES);
        #pragma unroll
        for (int ks=0;ks<4;ks++){
            int kb = ks*8;
            unsigned afr[2][4], bfr[8][2];
            #pragma unroll
            for (int im=0;im<2;im++){
                int m = wm + im*16;
                afr[im][0] = sA[(m+g  )*ASTRIDE + kb + tg];
                afr[im][1] = sA[(m+g+8)*ASTRIDE + kb + tg];
                afr[im][2] = sA[(m+g  )*ASTRIDE + kb + tg + 4];
                afr[im][3] = sA[(m+g+8)*ASTRIDE + kb + tg + 4];
            }
            #pragma unroll
            for (int jn=0;jn<8;jn++){
                int n = wn + jn*8;
                bfr[jn][0] = sB[(kb+tg  )*BSTRIDE + n + g];
                bfr[jn][1] = sB[(kb+tg+4)*BSTRIDE + n + g];
            }
            #pragma unroll
            for (int im=0;im<2;im++)
                #pragma unroll
                for (int jn=0;jn<8;jn++)
                    mma8(acc[im][jn], afr[im], bfr[jn]);
        }
        __syncthreads();
    }

    // ---- epilogue ----
    if (EPI==0){
        const int which = bn >> 10;                 // 0=q 1=k 2=v
        float* dst = (which==0) ? C : (which==1 ? Kp : Vp);
        const float sc = (which==0) ? scale : 1.0f;
        #pragma unroll
        for (int im=0;im<2;im++){
            #pragma unroll
            for (int eh=0;eh<2;eh++){
                int row = bm + wm + im*16 + g + eh*8;
                int b = row>>10, s = row&1023;
                #pragma unroll
                for (int jn=0;jn<8;jn++){
                    int col = (bn & 1023) + wn + jn*8 + 2*tg;
                    int h = col>>6, dk = col&63;
                    float2 o;
                    o.x = tf32r(acc[im][jn][eh*2  ]*sc);   // tf32: feeds attention mma
                    o.y = tf32r(acc[im][jn][eh*2+1]*sc);
                    *(float2*)(dst + (((size_t)((b<<4)+h)<<10) + s)*DKH + dk) = o;
                }
            }
        }
    } else {
        #pragma unroll
        for (int im=0;im<2;im++){
            #pragma unroll
            for (int eh=0;eh<2;eh++){
                int row = bm + wm + im*16 + g + eh*8;
                #pragma unroll
                for (int jn=0;jn<8;jn++){
                    int col = bn + wn + jn*8 + 2*tg;
                    size_t idx = (size_t)row*N + col;
                    float2 o;
                    o.x = acc[im][jn][eh*2  ];
                    o.y = acc[im][jn][eh*2+1];
                    if (EPI>=2){
                        o.x = fmaxf(o.x + __ldg(bias+col  ), 0.f);
                        o.y = fmaxf(o.y + __ldg(bias+col+1), 0.f);
                    }
                    if (EPI==2){ o.x = tf32r(o.x); o.y = tf32r(o.y); }
                    if (EPI==1 || EPI==3){
                        float2 rv = *(const float2*)(res + idx);
                        o.x += rv.x; o.y += rv.y;
                    }
                    *(float2*)(C + idx) = o;
                }
            }
        }
    }
}

// ---------------- tensor-core flash attention ----------------
// CTA: 64 q rows x one (b,h); 4 warps, each warp = m16 q rows.
// KV tiles of 64 double-buffered via cp.async; V transposed smem->smem.
// smem floats: sK[2][64*68] | sVr[2][64*68] | sVT[64*68] | sP[4][16*68]
#define AT_STR 68
#define AT_KTILE (64*AT_STR)          // 4352 floats
#define AT_SMEM_FLOATS (5*AT_KTILE + 4*16*AT_STR)   // 26112
#define AT_SMEM_BYTES (AT_SMEM_FLOATS*4)            // 104448

__global__ void __launch_bounds__(128,2) attn_tc(const int* __restrict__ mask){
    extern __shared__ __align__(16) float af[];
    float* sK  = af;
    float* sVr = af + 2*AT_KTILE;
    float* sVT = af + 4*AT_KTILE;
    float* sP  = af + 5*AT_KTILE;
    __shared__ int sM[2][64];

    const int tid = threadIdx.x;
    const int wq = tid>>5, lane = tid&31;
    const int g = lane>>2, tg = lane&3;
    const int bh = blockIdx.y;
    const int b = bh>>4, h = bh&15;
    const int qb = blockIdx.x*64;

    const float* kbase = g_k + ((size_t)bh<<10)*DKH;
    const float* vbase = g_v + ((size_t)bh<<10)*DKH;
    const int*   mbase = mask + (b<<10);
    const uint32_t sKu  = smem_u32(sK);
    const uint32_t sVru = smem_u32(sVr);

    // ---- load Q fragments into registers (rows qb+wq*16+g, +8) ----
    unsigned qf[8][4];
    {
        const float* q0 = g_q + (((size_t)bh<<10) + qb + wq*16 + g)*DKH;
        const float* q1 = q0 + 8*DKH;
        #pragma unroll
        for (int k8=0;k8<8;k8++){
            qf[k8][0] = __float_as_uint(q0[k8*8+tg]);
            qf[k8][1] = __float_as_uint(q1[k8*8+tg]);
            qf[k8][2] = __float_as_uint(q0[k8*8+tg+4]);
            qf[k8][3] = __float_as_uint(q1[k8*8+tg+4]);
        }
    }
    // ---- prologue: issue K0,V0; mask0 ----
    #pragma unroll
    for (int i=0;i<8;i++){
        int idx = i*128 + tid;
        int r = idx>>4, c4 = idx&15;
        cpa16(sKu  + (uint32_t)(r*AT_STR + c4*4)*4u, kbase + (size_t)r*DKH + c4*4);
        cpa16(sVru + (uint32_t)(r*AT_STR + c4*4)*4u, vbase + (size_t)r*DKH + c4*4);
    }
    asm volatile("cp.async.commit_group;" ::: "memory");
    if (tid < 64) sM[0][tid] = mbase[tid];
    asm volatile("cp.async.wait_group 0;" ::: "memory");
    __syncthreads();

    float oA[8][4];
    #pragma unroll
    for (int nb=0;nb<8;nb++){ oA[nb][0]=0.f; oA[nb][1]=0.f; oA[nb][2]=0.f; oA[nb][3]=0.f; }
    float mr0 = -1e30f, mr1 = -1e30f, l0 = 0.f, l1 = 0.f;
    float* sPw = sP + wq*16*AT_STR;

    for (int kt=0;kt<16;kt++){
        const int st = kt & 1;
        // prefetch kt+1 (opposite stage; safe: all warps past end barrier of kt-1)
        if (kt < 15){
            const float* kn = kbase + (size_t)(kt+1)*64*DKH;
            const float* vn = vbase + (size_t)(kt+1)*64*DKH;
            uint32_t dK = sKu  + (uint32_t)(st^1)*AT_KTILE*4u;
            uint32_t dV = sVru + (uint32_t)(st^1)*AT_KTILE*4u;
            #pragma unroll
            for (int i=0;i<8;i++){
                int idx = i*128 + tid;
                int r = idx>>4, c4 = idx&15;
                cpa16(dK + (uint32_t)(r*AT_STR + c4*4)*4u, kn + (size_t)r*DKH + c4*4);
                cpa16(dV + (uint32_t)(r*AT_STR + c4*4)*4u, vn + (size_t)r*DKH + c4*4);
            }
            asm volatile("cp.async.commit_group;" ::: "memory");
        }
        // ---- S = Q K^T (16x64 per warp) ----
        float s[8][4];
        #pragma unroll
        for (int nb=0;nb<8;nb++){ s[nb][0]=0.f; s[nb][1]=0.f; s[nb][2]=0.f; s[nb][3]=0.f; }
        const float* sKs = sK + st*AT_KTILE;
        #pragma unroll
        for (int k8=0;k8<8;k8++){
            unsigned bfr[8][2];
            #pragma unroll
            for (int nb=0;nb<8;nb++){
                bfr[nb][0] = __float_as_uint(sKs[(nb*8+g)*AT_STR + k8*8+tg  ]);
                bfr[nb][1] = __float_as_uint(sKs[(nb*8+g)*AT_STR + k8*8+tg+4]);
            }
            #pragma unroll
            for (int nb=0;nb<8;nb++) mma8(s[nb], qf[k8], bfr[nb]);
        }
        // ---- mask + online softmax ----
        float rmax0 = -1e30f, rmax1 = -1e30f;
        #pragma unroll
        for (int nb=0;nb<8;nb++){
            int c0 = nb*8 + 2*tg;
            if (sM[st][c0  ]){ s[nb][0] = -1e30f; s[nb][2] = -1e30f; }
            if (sM[st][c0+1]){ s[nb][1] = -1e30f; s[nb][3] = -1e30f; }
            rmax0 = fmaxf(rmax0, fmaxf(s[nb][0], s[nb][1]));
            rmax1 = fmaxf(rmax1, fmaxf(s[nb][2], s[nb][3]));
        }
        rmax0 = fmaxf(rmax0, __shfl_xor_sync(0xffffffffu, rmax0, 1));
        rmax0 = fmaxf(rmax0, __shfl_xor_sync(0xffffffffu, rmax0, 2));
        rmax1 = fmaxf(rmax1, __shfl_xor_sync(0xffffffffu, rmax1, 1));
        rmax1 = fmaxf(rmax1, __shfl_xor_sync(0xffffffffu, rmax1, 2));
        float nm0 = fmaxf(mr0, rmax0), nm1 = fmaxf(mr1, rmax1);
        float corr0 = __expf(mr0 - nm0), corr1 = __expf(mr1 - nm1);
        mr0 = nm0; mr1 = nm1;
        float sum0 = 0.f, sum1 = 0.f;
        #pragma unroll
        for (int nb=0;nb<8;nb++){
            float p0 = __expf(s[nb][0]-nm0), p1 = __expf(s[nb][1]-nm0);
            float p2 = __expf(s[nb][2]-nm1), p3 = __expf(s[nb][3]-nm1);
            sum0 += p0+p1; sum1 += p2+p3;
            *(float2*)(sPw + (g  )*AT_STR + nb*8 + 2*tg) = make_float2(tf32r(p0), tf32r(p1));
            *(float2*)(sPw + (g+8)*AT_STR + nb*8 + 2*tg) = make_float2(tf32r(p2), tf32r(p3));
        }
        sum0 += __shfl_xor_sync(0xffffffffu, sum0, 1);
        sum0 += __shfl_xor_sync(0xffffffffu, sum0, 2);
        sum1 += __shfl_xor_sync(0xffffffffu, sum1, 1);
        sum1 += __shfl_xor_sync(0xffffffffu, sum1, 2);
        l0 = l0*corr0 + sum0;
        l1 = l1*corr1 + sum1;
        #pragma unroll
        for (int nb=0;nb<8;nb++){
            oA[nb][0]*=corr0; oA[nb][1]*=corr0; oA[nb][2]*=corr1; oA[nb][3]*=corr1;
        }
        __syncthreads();   // T1: Vraw(st) settled readers; sVT free (prev PV done)
        // ---- transpose V(st) -> sVT [d][kv], conflict-free writes ----
        {
            const float* vs = sVr + st*AT_KTILE;
            #pragma unroll
            for (int i=0;i<8;i++){
                int idx = i*128 + tid;
                int c4 = idx>>6, r = idx&63;
                float4 vv = *(const float4*)(vs + r*AT_STR + c4*4);
                sVT[(c4*4  )*AT_STR + r] = vv.x;
                sVT[(c4*4+1)*AT_STR + r] = vv.y;
                sVT[(c4*4+2)*AT_STR + r] = vv.z;
                sVT[(c4*4+3)*AT_STR + r] = vv.w;
            }
            if (kt < 15 && tid < 64) sM[st^1][tid] = mbase[(kt+1)*64 + tid];
        }
        __syncthreads();   // T2: sVT visible
        // ---- O += P V ----
        #pragma unroll
        for (int k8=0;k8<8;k8++){
            unsigned afr[4], bfr[8][2];
            afr[0] = __float_as_uint(sPw[(g  )*AT_STR + k8*8+tg  ]);
            afr[1] = __float_as_uint(sPw[(g+8)*AT_STR + k8*8+tg  ]);
            afr[2] = __float_as_uint(sPw[(g  )*AT_STR + k8*8+tg+4]);
            afr[3] = __float_as_uint(sPw[(g+8)*AT_STR + k8*8+tg+4]);
            #pragma unroll
            for (int nb=0;nb<8;nb++){
                bfr[nb][0] = __float_as_uint(sVT[(nb*8+g)*AT_STR + k8*8+tg  ]);
                bfr[nb][1] = __float_as_uint(sVT[(nb*8+g)*AT_STR + k8*8+tg+4]);
            }
            #pragma unroll
            for (int nb=0;nb<8;nb++) mma8(oA[nb], afr, bfr[nb]);
        }
        asm volatile("cp.async.wait_group 0;" ::: "memory");
        __syncthreads();   // T3: next-stage K/V visible to all threads
    }
    // ---- output ----
    float inv0 = 1.f/l0, inv1 = 1.f/l1;
    int s0 = qb + wq*16 + g;
    float* out0 = g_ctx + (((size_t)(b<<10)) + s0)*DMODEL + h*DKH;
    float* out1 = out0 + 8*DMODEL;
    #pragma unroll
    for (int nb=0;nb<8;nb++){
        int c0 = nb*8 + 2*tg;
        *(float2*)(out0 + c0) = make_float2(tf32r(oA[nb][0]*inv0), tf32r(oA[nb][1]*inv0));
        *(float2*)(out1 + c0) = make_float2(tf32r(oA[nb][2]*inv1), tf32r(oA[nb][3]*inv1));
    }
}

// ---------------- launch ----------------
extern "C" void kernel_launch(void* const* d_in, const int* in_sizes, int n_in,
                              void* d_out, int out_size){
    const float* x    = (const float*)d_in[0];
    const int*   mask = (const int*)  d_in[1];
    const float* Wq   = (const float*)d_in[2];
    const float* Wk   = (const float*)d_in[3];
    const float* Wv   = (const float*)d_in[4];
    const float* Wo   = (const float*)d_in[5];
    const float* ln1g = (const float*)d_in[6];
    const float* ln1b = (const float*)d_in[7];
    const float* ln2g = (const float*)d_in[8];
    const float* ln2b = (const float*)d_in[9];
    const float* c1w  = (const float*)d_in[10];
    const float* c1b  = (const float*)d_in[11];
    const float* c2w  = (const float*)d_in[12];
    const float* c2b  = (const float*)d_in[13];
    float* out = (float*)d_out;

    float *xn, *q, *k, *v, *ctx, *x1, *xn2, *h1;
    float *wqkv, *wo, *c1, *c2;
    cudaGetSymbolAddress((void**)&xn,  g_xn);
    cudaGetSymbolAddress((void**)&q,   g_q);
    cudaGetSymbolAddress((void**)&k,   g_k);
    cudaGetSymbolAddress((void**)&v,   g_v);
    cudaGetSymbolAddress((void**)&ctx, g_ctx);
    cudaGetSymbolAddress((void**)&x1,  g_x1);
    cudaGetSymbolAddress((void**)&xn2, g_xn2);
    cudaGetSymbolAddress((void**)&h1,  g_h1);
    cudaGetSymbolAddress((void**)&wqkv,g_wqkv);
    cudaGetSymbolAddress((void**)&wo,  g_wo);
    cudaGetSymbolAddress((void**)&c1,  g_c1);
    cudaGetSymbolAddress((void**)&c2,  g_c2);

    cudaFuncSetAttribute(gemm_p<0,0,0>,  cudaFuncAttributeMaxDynamicSharedMemorySize, SMEM_GEMM);
    cudaFuncSetAttribute(gemm_p<0,1,0>,  cudaFuncAttributeMaxDynamicSharedMemorySize, SMEM_GEMM);
    cudaFuncSetAttribute(gemm_p<1,2,10>, cudaFuncAttributeMaxDynamicSharedMemorySize, SMEM_GEMM);
    cudaFuncSetAttribute(gemm_p<1,3,12>, cudaFuncAttributeMaxDynamicSharedMemorySize, SMEM_GEMM);
    cudaFuncSetAttribute(attn_tc,        cudaFuncAttributeMaxDynamicSharedMemorySize, AT_SMEM_BYTES);

    // 0) weight prep
    pack_w<<<1024, 256>>>((const float4*)Wq, (float4*)wqkv, 0);
    pack_w<<<1024, 256>>>((const float4*)Wk, (float4*)wqkv, 256);
    pack_w<<<1024, 256>>>((const float4*)Wv, (float4*)wqkv, 512);
    round_copy<<<1024, 256>>>((const float4*)Wo, (float4*)wo, DMODEL*DMODEL/4);
    round_copy<<<(3*DMODEL*FF/4 + 255)/256, 256>>>((const float4*)c1w, (float4*)c1, 3*DMODEL*FF/4);
    round_copy<<<(3*FF*DMODEL/4 + 255)/256, 256>>>((const float4*)c2w, (float4*)c2, 3*FF*DMODEL/4);

    // 1) LN1
    ln_kernel<<<ROWS,256>>>(x, ln1g, ln1b, xn);

    // 2) fused QKV projection
    dim3 gqkv(3*DMODEL/BN, ROWS/BM);
    gemm_p<0,0,0><<<gqkv,256,SMEM_GEMM>>>(xn, wqkv, q, nullptr, nullptr,
                                          DMODEL, 3*DMODEL, 0.125f, k, v);

    // 3) attention (tensor-core flash)
    dim3 ga(SEQ/64, BATCH*NH);
    attn_tc<<<ga,128,AT_SMEM_BYTES>>>(mask);

    // 4) output projection + residual
    dim3 go(DMODEL/BN, ROWS/BM);
    gemm_p<0,1,0><<<go,256,SMEM_GEMM>>>(ctx, wo, x1, nullptr, x,
                                        DMODEL, DMODEL, 1.0f, nullptr, nullptr);

    // 5) LN2
    ln_kernel<<<ROWS,256>>>(x1, ln2g, ln2b, xn2);

    // 6) conv1
    gemm_p<1,2,10><<<dim3(FF/BN, ROWS/BM),256,SMEM_GEMM>>>(xn2, c1, h1, c1b, nullptr,
                                        3*DMODEL, FF, 1.0f, nullptr, nullptr);

    // 7) conv2 -> final output
    gemm_p<1,3,12><<<dim3(DMODEL/BN, ROWS/BM),256,SMEM_GEMM>>>(h1, c2, out, c2b, x1,
                                        3*FF, DMODEL, 1.0f, nullptr, nullptr);
}

// round 11
// speedup vs baseline: 2.3923x; 1.1569x over previous
#include <cuda_runtime.h>
#include <math.h>
#include <stdint.h>

#define BATCH 8
#define SEQ 1024
#define DMODEL 1024
#define NH 16
#define DKH 64
#define FF 4096
#define ROWS (BATCH*SEQ)

// ---------------- scratch (device globals: allocation-free rule) ----------------
__device__ float g_xn [(size_t)ROWS*DMODEL];
__device__ float g_q  [(size_t)ROWS*DMODEL];   // [B,H,S,DK]
__device__ float g_k  [(size_t)ROWS*DMODEL];   // [B,H,S,DK]
__device__ float g_v  [(size_t)ROWS*DMODEL];   // [B,H,S,DK]
__device__ float g_ctx[(size_t)ROWS*DMODEL];   // [B,S,D]
__device__ float g_x1 [(size_t)ROWS*DMODEL];
__device__ float g_xn2[(size_t)ROWS*DMODEL];
__device__ float g_h1 [(size_t)ROWS*FF];
// tf32-prerounded weights
__device__ float g_wqkv[(size_t)DMODEL*3*DMODEL];   // [K=1024, N=3072] packed q|k|v
__device__ float g_wo  [(size_t)DMODEL*DMODEL];     // [K,N]
__device__ float g_c1  [(size_t)3*DMODEL*FF];       // [K=3072, N=4096]
__device__ float g_c2  [(size_t)3*FF*DMODEL];       // [K=12288, N=1024]

// ---------------- helpers ----------------
__device__ __forceinline__ float tf32r(float f){
    unsigned u; asm("cvt.rna.tf32.f32 %0, %1;" : "=r"(u) : "f"(f));
    return __uint_as_float(u);
}
__device__ __forceinline__ uint32_t smem_u32(const void* p){
    uint32_t a;
    asm("{ .reg .u64 t; cvta.to.shared.u64 t, %1; cvt.u32.u64 %0, t; }" : "=r"(a) : "l"(p));
    return a;
}
__device__ __forceinline__ void mma8(float* d, const unsigned* a, const unsigned* b){
    asm volatile("mma.sync.aligned.m16n8k8.row.col.f32.tf32.tf32.f32 "
        "{%0,%1,%2,%3},{%4,%5,%6,%7},{%8,%9},{%0,%1,%2,%3};\n"
        : "+f"(d[0]), "+f"(d[1]), "+f"(d[2]), "+f"(d[3])
        : "r"(a[0]), "r"(a[1]), "r"(a[2]), "r"(a[3]), "r"(b[0]), "r"(b[1]));
}
__device__ __forceinline__ void cpa16(uint32_t so, const float* src){
    asm volatile("cp.async.cg.shared.global [%0], [%1], 16, %2;"
                 :: "r"(so), "l"(src), "r"(16));
}

// ---------------- weight preprocessing ----------------
__global__ void __launch_bounds__(256) round_copy(const float4* __restrict__ in,
        float4* __restrict__ out, int n4){
    int i = blockIdx.x*256 + threadIdx.x;
    if (i < n4){
        float4 v = in[i];
        v.x = tf32r(v.x); v.y = tf32r(v.y); v.z = tf32r(v.z); v.w = tf32r(v.w);
        out[i] = v;
    }
}
__global__ void __launch_bounds__(256) pack_w(const float4* __restrict__ in,
        float4* __restrict__ out, int off4){
    int i = blockIdx.x*256 + threadIdx.x;
    int kk = i >> 8, n4 = i & 255;
    float4 v = in[i];
    v.x = tf32r(v.x); v.y = tf32r(v.y); v.z = tf32r(v.z); v.w = tf32r(v.w);
    out[kk*768 + off4 + n4] = v;
}

// ---------------- LayerNorm ----------------
__global__ void __launch_bounds__(256) ln_kernel(const float* __restrict__ x,
        const float* __restrict__ gg, const float* __restrict__ bb, float* __restrict__ y){
    __shared__ float red[8];
    __shared__ float bc;
    int row = blockIdx.x;
    const float4* xr = (const float4*)(x + (size_t)row*DMODEL);
    float4 v = xr[threadIdx.x];
    float s = v.x+v.y+v.z+v.w;
    #pragma unroll
    for (int o=16;o;o>>=1) s += __shfl_xor_sync(0xffffffffu, s, o);
    if ((threadIdx.x&31)==0) red[threadIdx.x>>5] = s;
    __syncthreads();
    if (threadIdx.x==0){ float t=0; for(int i=0;i<8;i++) t+=red[i]; bc = t*(1.0f/DMODEL); }
    __syncthreads();
    float mu = bc;
    float dx0=v.x-mu, dx1=v.y-mu, dx2=v.z-mu, dx3=v.w-mu;
    float q = dx0*dx0+dx1*dx1+dx2*dx2+dx3*dx3;
    #pragma unroll
    for (int o=16;o;o>>=1) q += __shfl_xor_sync(0xffffffffu, q, o);
    if ((threadIdx.x&31)==0) red[threadIdx.x>>5] = q;
    __syncthreads();
    if (threadIdx.x==0){ float t=0; for(int i=0;i<8;i++) t+=red[i]; bc = rsqrtf(t*(1.0f/DMODEL) + 1e-6f); }
    __syncthreads();
    float rs = bc;
    const float4 g4 = ((const float4*)gg)[threadIdx.x];
    const float4 b4 = ((const float4*)bb)[threadIdx.x];
    float4 o;
    o.x = tf32r(dx0*rs*g4.x + b4.x);
    o.y = tf32r(dx1*rs*g4.y + b4.y);
    o.z = tf32r(dx2*rs*g4.z + b4.z);
    o.w = tf32r(dx3*rs*g4.w + b4.w);
    ((float4*)(y + (size_t)row*DMODEL))[threadIdx.x] = o;
}

// ---------------- pipelined TF32 mma.sync GEMM: 128M x 256N, BK=32, 3-stage ----------------
// 8 warps in 2(M) x 4(N) grid; warp tile 64x64 (4x m16, 8x n8).
// BSTRIDE = BN+8 (stride%32==8 -> bank 8*tg+g, perfect permutation, conflict-free)
#define BM 128
#define BN 256
#define BK 32
#define ASTRIDE 36                    // bank 4g+tg: conflict-free
#define BSTRIDE (BN+8)                // 264
#define ABYTES (BM*ASTRIDE*4)         // 18432
#define BBYTES (BK*BSTRIDE*4)         // 33792
#define STAGEB (ABYTES+BBYTES)        // 52224
#define NSTAGE 3
#define SMEM_GEMM (NSTAGE*STAGEB)     // 156672

template<int AMODE,int CSH>
__device__ __forceinline__ void load_chunk(const float* __restrict__ A,
        const float* __restrict__ Bw, int Kd, int N, int bm, int bn, int c,
        uint32_t smem_base, int tid){
    const int k0 = c*BK;
    const uint32_t st = smem_base + (uint32_t)(c % NSTAGE)*STAGEB;
    // A tile: 128 rows x 32 floats = 1024 float4, 4/thread
    #pragma unroll
    for (int i=0;i<4;i++){
        int idx = i*256 + tid;
        int row = idx>>3, seg = idx&7;
        uint32_t so = st + (uint32_t)(row*ASTRIDE + seg*4)*4u;
        const float* src; int sz = 16;
        if (AMODE==0){
            src = A + (size_t)(bm+row)*Kd + k0 + seg*4;
        } else {
            int m = bm+row, b = m>>10, s = m&1023;
            int kw = k0 >> CSH;
            int cin = (k0 & ((1<<CSH)-1)) + seg*4;
            int ss = s + kw - 1;
            src = A + (((size_t)((b<<10)+ss)) << CSH) + cin;
            if ((unsigned)ss >= 1024u) sz = 0;
        }
        asm volatile("cp.async.cg.shared.global [%0], [%1], 16, %2;"
                     :: "r"(so), "l"(src), "r"(sz));
    }
    // B tile: 32 rows x 256 floats = 2048 float4, 8/thread
    #pragma unroll
    for (int i=0;i<8;i++){
        int idx = i*256 + tid;
        int kk = idx>>6, n4 = idx&63;
        uint32_t so = st + (uint32_t)ABYTES + (uint32_t)(kk*BSTRIDE + n4*4)*4u;
        const float* src = Bw + (size_t)(k0+kk)*N + bn + n4*4;
        asm volatile("cp.async.cg.shared.global [%0], [%1], 16, %2;"
                     :: "r"(so), "l"(src), "r"(16));
    }
    asm volatile("cp.async.commit_group;" ::: "memory");
}

template<int AMODE,int EPI,int CSH>
__global__ void __launch_bounds__(256,1)
gemm_p(const float* __restrict__ A, const float* __restrict__ Bw,
       float* __restrict__ C, const float* __restrict__ bias,
       const float* __restrict__ res, int Kd, int N, float scale,
       float* __restrict__ Kp, float* __restrict__ Vp)
{
    extern __shared__ __align__(16) char smem[];
    uint32_t smem_base = smem_u32(smem);
    const int tid = threadIdx.x;
    const int bm = blockIdx.y*BM, bn = blockIdx.x*BN;
    const int warp = tid>>5, lane = tid&31;
    const int wm = (warp&1)*64, wn = (warp>>1)*64;
    const int g = lane>>2, tg = lane&3;
    const int NC = Kd/BK;

    float acc[4][8][4];
    #pragma unroll
    for (int i=0;i<4;i++)
        #pragma unroll
        for (int j=0;j<8;j++)
            #pragma unroll
            for (int e=0;e<4;e++) acc[i][j][e]=0.f;

    load_chunk<AMODE,CSH>(A,Bw,Kd,N,bm,bn,0,smem_base,tid);
    load_chunk<AMODE,CSH>(A,Bw,Kd,N,bm,bn,1,smem_base,tid);

    for (int c=0;c<NC;c++){
        if (c < NC-1){ asm volatile("cp.async.wait_group 1;" ::: "memory"); }
        else         { asm volatile("cp.async.wait_group 0;" ::: "memory"); }
        __syncthreads();
        if (c+2 < NC) load_chunk<AMODE,CSH>(A,Bw,Kd,N,bm,bn,c+2,smem_base,tid);
        const unsigned* sA = (const unsigned*)(smem + (size_t)(c%NSTAGE)*STAGEB);
        const unsigned* sB = (const unsigned*)(smem + (size_t)(c%NSTAGE)*STAGEB + ABYTES);
        #pragma unroll
        for (int ks=0;ks<4;ks++){
            int kb = ks*8;
            unsigned bfr[8][2];
            #pragma unroll
            for (int nb=0;nb<8;nb++){
                int n = wn + nb*8;
                bfr[nb][0] = sB[(kb+tg  )*BSTRIDE + n + g];
                bfr[nb][1] = sB[(kb+tg+4)*BSTRIDE + n + g];
            }
            #pragma unroll
            for (int im=0;im<4;im++){
                int m = wm + im*16;
                unsigned afr[4];
                afr[0] = sA[(m+g  )*ASTRIDE + kb + tg];
                afr[1] = sA[(m+g+8)*ASTRIDE + kb + tg];
                afr[2] = sA[(m+g  )*ASTRIDE + kb + tg + 4];
                afr[3] = sA[(m+g+8)*ASTRIDE + kb + tg + 4];
                #pragma unroll
                for (int nb=0;nb<8;nb++)
                    mma8(acc[im][nb], afr, bfr[nb]);
            }
        }
        __syncthreads();
    }

    // ---- epilogue ----
    if (EPI==0){
        const int which = bn >> 10;                 // 0=q 1=k 2=v (BN=256 divides 1024)
        float* dst = (which==0) ? C : (which==1 ? Kp : Vp);
        const float sc = (which==0) ? scale : 1.0f;
        #pragma unroll
        for (int im=0;im<4;im++){
            #pragma unroll
            for (int eh=0;eh<2;eh++){
                int row = bm + wm + im*16 + g + eh*8;
                int b = row>>10, s = row&1023;
                #pragma unroll
                for (int nb=0;nb<8;nb++){
                    int col = (bn & 1023) + wn + nb*8 + 2*tg;
                    int h = col>>6, dk = col&63;
                    float2 o;
                    o.x = tf32r(acc[im][nb][eh*2  ]*sc);
                    o.y = tf32r(acc[im][nb][eh*2+1]*sc);
                    *(float2*)(dst + (((size_t)((b<<4)+h)<<10) + s)*DKH + dk) = o;
                }
            }
        }
    } else {
        #pragma unroll
        for (int im=0;im<4;im++){
            #pragma unroll
            for (int eh=0;eh<2;eh++){
                int row = bm + wm + im*16 + g + eh*8;
                #pragma unroll
                for (int nb=0;nb<8;nb++){
                    int col = bn + wn + nb*8 + 2*tg;
                    size_t idx = (size_t)row*N + col;
                    float2 o;
                    o.x = acc[im][nb][eh*2  ];
                    o.y = acc[im][nb][eh*2+1];
                    if (EPI>=2){
                        o.x = fmaxf(o.x + __ldg(bias+col  ), 0.f);
                        o.y = fmaxf(o.y + __ldg(bias+col+1), 0.f);
                    }
                    if (EPI==2){ o.x = tf32r(o.x); o.y = tf32r(o.y); }
                    if (EPI==1 || EPI==3){
                        float2 rv = *(const float2*)(res + idx);
                        o.x += rv.x; o.y += rv.y;
                    }
                    *(float2*)(C + idx) = o;
                }
            }
        }
    }
}

// ---------------- tensor-core flash attention (unchanged from R9) ----------------
#define AT_STR 68
#define AT_KTILE (64*AT_STR)
#define AT_SMEM_FLOATS (5*AT_KTILE + 4*16*AT_STR)
#define AT_SMEM_BYTES (AT_SMEM_FLOATS*4)

__global__ void __launch_bounds__(128,2) attn_tc(const int* __restrict__ mask){
    extern __shared__ __align__(16) float af[];
    float* sK  = af;
    float* sVr = af + 2*AT_KTILE;
    float* sVT = af + 4*AT_KTILE;
    float* sP  = af + 5*AT_KTILE;
    __shared__ int sM[2][64];

    const int tid = threadIdx.x;
    const int wq = tid>>5, lane = tid&31;
    const int g = lane>>2, tg = lane&3;
    const int bh = blockIdx.y;
    const int b = bh>>4, h = bh&15;
    const int qb = blockIdx.x*64;

    const float* kbase = g_k + ((size_t)bh<<10)*DKH;
    const float* vbase = g_v + ((size_t)bh<<10)*DKH;
    const int*   mbase = mask + (b<<10);
    const uint32_t sKu  = smem_u32(sK);
    const uint32_t sVru = smem_u32(sVr);

    unsigned qf[8][4];
    {
        const float* q0 = g_q + (((size_t)bh<<10) + qb + wq*16 + g)*DKH;
        const float* q1 = q0 + 8*DKH;
        #pragma unroll
        for (int k8=0;k8<8;k8++){
            qf[k8][0] = __float_as_uint(q0[k8*8+tg]);
            qf[k8][1] = __float_as_uint(q1[k8*8+tg]);
            qf[k8][2] = __float_as_uint(q0[k8*8+tg+4]);
            qf[k8][3] = __float_as_uint(q1[k8*8+tg+4]);
        }
    }
    #pragma unroll
    for (int i=0;i<8;i++){
        int idx = i*128 + tid;
        int r = idx>>4, c4 = idx&15;
        cpa16(sKu  + (uint32_t)(r*AT_STR + c4*4)*4u, kbase + (size_t)r*DKH + c4*4);
        cpa16(sVru + (uint32_t)(r*AT_STR + c4*4)*4u, vbase + (size_t)r*DKH + c4*4);
    }
    asm volatile("cp.async.commit_group;" ::: "memory");
    if (tid < 64) sM[0][tid] = mbase[tid];
    asm volatile("cp.async.wait_group 0;" ::: "memory");
    __syncthreads();

    float oA[8][4];
    #pragma unroll
    for (int nb=0;nb<8;nb++){ oA[nb][0]=0.f; oA[nb][1]=0.f; oA[nb][2]=0.f; oA[nb][3]=0.f; }
    float mr0 = -1e30f, mr1 = -1e30f, l0 = 0.f, l1 = 0.f;
    float* sPw = sP + wq*16*AT_STR;

    for (int kt=0;kt<16;kt++){
        const int st = kt & 1;
        if (kt < 15){
            const float* kn = kbase + (size_t)(kt+1)*64*DKH;
            const float* vn = vbase + (size_t)(kt+1)*64*DKH;
            uint32_t dK = sKu  + (uint32_t)(st^1)*AT_KTILE*4u;
            uint32_t dV = sVru + (uint32_t)(st^1)*AT_KTILE*4u;
            #pragma unroll
            for (int i=0;i<8;i++){
                int idx = i*128 + tid;
                int r = idx>>4, c4 = idx&15;
                cpa16(dK + (uint32_t)(r*AT_STR + c4*4)*4u, kn + (size_t)r*DKH + c4*4);
                cpa16(dV + (uint32_t)(r*AT_STR + c4*4)*4u, vn + (size_t)r*DKH + c4*4);
            }
            asm volatile("cp.async.commit_group;" ::: "memory");
        }
        float s[8][4];
        #pragma unroll
        for (int nb=0;nb<8;nb++){ s[nb][0]=0.f; s[nb][1]=0.f; s[nb][2]=0.f; s[nb][3]=0.f; }
        const float* sKs = sK + st*AT_KTILE;
        #pragma unroll
        for (int k8=0;k8<8;k8++){
            unsigned bfr[8][2];
            #pragma unroll
            for (int nb=0;nb<8;nb++){
                bfr[nb][0] = __float_as_uint(sKs[(nb*8+g)*AT_STR + k8*8+tg  ]);
                bfr[nb][1] = __float_as_uint(sKs[(nb*8+g)*AT_STR + k8*8+tg+4]);
            }
            #pragma unroll
            for (int nb=0;nb<8;nb++) mma8(s[nb], qf[k8], bfr[nb]);
        }
        float rmax0 = -1e30f, rmax1 = -1e30f;
        #pragma unroll
        for (int nb=0;nb<8;nb++){
            int c0 = nb*8 + 2*tg;
            if (sM[st][c0  ]){ s[nb][0] = -1e30f; s[nb][2] = -1e30f; }
            if (sM[st][c0+1]){ s[nb][1] = -1e30f; s[nb][3] = -1e30f; }
            rmax0 = fmaxf(rmax0, fmaxf(s[nb][0], s[nb][1]));
            rmax1 = fmaxf(rmax1, fmaxf(s[nb][2], s[nb][3]));
        }
        rmax0 = fmaxf(rmax0, __shfl_xor_sync(0xffffffffu, rmax0, 1));
        rmax0 = fmaxf(rmax0, __shfl_xor_sync(0xffffffffu, rmax0, 2));
        rmax1 = fmaxf(rmax1, __shfl_xor_sync(0xffffffffu, rmax1, 1));
        rmax1 = fmaxf(rmax1, __shfl_xor_sync(0xffffffffu, rmax1, 2));
        float nm0 = fmaxf(mr0, rmax0), nm1 = fmaxf(mr1, rmax1);
        float corr0 = __expf(mr0 - nm0), corr1 = __expf(mr1 - nm1);
        mr0 = nm0; mr1 = nm1;
        float sum0 = 0.f, sum1 = 0.f;
        #pragma unroll
        for (int nb=0;nb<8;nb++){
            float p0 = __expf(s[nb][0]-nm0), p1 = __expf(s[nb][1]-nm0);
            float p2 = __expf(s[nb][2]-nm1), p3 = __expf(s[nb][3]-nm1);
            sum0 += p0+p1; sum1 += p2+p3;
            *(float2*)(sPw + (g  )*AT_STR + nb*8 + 2*tg) = make_float2(tf32r(p0), tf32r(p1));
            *(float2*)(sPw + (g+8)*AT_STR + nb*8 + 2*tg) = make_float2(tf32r(p2), tf32r(p3));
        }
        sum0 += __shfl_xor_sync(0xffffffffu, sum0, 1);
        sum0 += __shfl_xor_sync(0xffffffffu, sum0, 2);
        sum1 += __shfl_xor_sync(0xffffffffu, sum1, 1);
        sum1 += __shfl_xor_sync(0xffffffffu, sum1, 2);
        l0 = l0*corr0 + sum0;
        l1 = l1*corr1 + sum1;
        #pragma unroll
        for (int nb=0;nb<8;nb++){
            oA[nb][0]*=corr0; oA[nb][1]*=corr0; oA[nb][2]*=corr1; oA[nb][3]*=corr1;
        }
        __syncthreads();
        {
            const float* vs = sVr + st*AT_KTILE;
            #pragma unroll
            for (int i=0;i<8;i++){
                int idx = i*128 + tid;
                int c4 = idx>>6, r = idx&63;
                float4 vv = *(const float4*)(vs + r*AT_STR + c4*4);
                sVT[(c4*4  )*AT_STR + r] = vv.x;
                sVT[(c4*4+1)*AT_STR + r] = vv.y;
                sVT[(c4*4+2)*AT_STR + r] = vv.z;
                sVT[(c4*4+3)*AT_STR + r] = vv.w;
            }
            if (kt < 15 && tid < 64) sM[st^1][tid] = mbase[(kt+1)*64 + tid];
        }
        __syncthreads();
        #pragma unroll
        for (int k8=0;k8<8;k8++){
            unsigned afr[4], bfr[8][2];
            afr[0] = __float_as_uint(sPw[(g  )*AT_STR + k8*8+tg  ]);
            afr[1] = __float_as_uint(sPw[(g+8)*AT_STR + k8*8+tg  ]);
            afr[2] = __float_as_uint(sPw[(g  )*AT_STR + k8*8+tg+4]);
            afr[3] = __float_as_uint(sPw[(g+8)*AT_STR + k8*8+tg+4]);
            #pragma unroll
            for (int nb=0;nb<8;nb++){
                bfr[nb][0] = __float_as_uint(sVT[(nb*8+g)*AT_STR + k8*8+tg  ]);
                bfr[nb][1] = __float_as_uint(sVT[(nb*8+g)*AT_STR + k8*8+tg+4]);
            }
            #pragma unroll
            for (int nb=0;nb<8;nb++) mma8(oA[nb], afr, bfr[nb]);
        }
        asm volatile("cp.async.wait_group 0;" ::: "memory");
        __syncthreads();
    }
    float inv0 = 1.f/l0, inv1 = 1.f/l1;
    int s0 = qb + wq*16 + g;
    float* out0 = g_ctx + (((size_t)(b<<10)) + s0)*DMODEL + h*DKH;
    float* out1 = out0 + 8*DMODEL;
    #pragma unroll
    for (int nb=0;nb<8;nb++){
        int c0 = nb*8 + 2*tg;
        *(float2*)(out0 + c0) = make_float2(tf32r(oA[nb][0]*inv0), tf32r(oA[nb][1]*inv0));
        *(float2*)(out1 + c0) = make_float2(tf32r(oA[nb][2]*inv1), tf32r(oA[nb][3]*inv1));
    }
}

// ---------------- launch ----------------
extern "C" void kernel_launch(void* const* d_in, const int* in_sizes, int n_in,
                              void* d_out, int out_size){
    const float* x    = (const float*)d_in[0];
    const int*   mask = (const int*)  d_in[1];
    const float* Wq   = (const float*)d_in[2];
    const float* Wk   = (const float*)d_in[3];
    const float* Wv   = (const float*)d_in[4];
    const float* Wo   = (const float*)d_in[5];
    const float* ln1g = (const float*)d_in[6];
    const float* ln1b = (const float*)d_in[7];
    const float* ln2g = (const float*)d_in[8];
    const float* ln2b = (const float*)d_in[9];
    const float* c1w  = (const float*)d_in[10];
    const float* c1b  = (const float*)d_in[11];
    const float* c2w  = (const float*)d_in[12];
    const float* c2b  = (const float*)d_in[13];
    float* out = (float*)d_out;

    float *xn, *q, *k, *v, *ctx, *x1, *xn2, *h1;
    float *wqkv, *wo, *c1, *c2;
    cudaGetSymbolAddress((void**)&xn,  g_xn);
    cudaGetSymbolAddress((void**)&q,   g_q);
    cudaGetSymbolAddress((void**)&k,   g_k);
    cudaGetSymbolAddress((void**)&v,   g_v);
    cudaGetSymbolAddress((void**)&ctx, g_ctx);
    cudaGetSymbolAddress((void**)&x1,  g_x1);
    cudaGetSymbolAddress((void**)&xn2, g_xn2);
    cudaGetSymbolAddress((void**)&h1,  g_h1);
    cudaGetSymbolAddress((void**)&wqkv,g_wqkv);
    cudaGetSymbolAddress((void**)&wo,  g_wo);
    cudaGetSymbolAddress((void**)&c1,  g_c1);
    cudaGetSymbolAddress((void**)&c2,  g_c2);

    cudaFuncSetAttribute(gemm_p<0,0,0>,  cudaFuncAttributeMaxDynamicSharedMemorySize, SMEM_GEMM);
    cudaFuncSetAttribute(gemm_p<0,1,0>,  cudaFuncAttributeMaxDynamicSharedMemorySize, SMEM_GEMM);
    cudaFuncSetAttribute(gemm_p<1,2,10>, cudaFuncAttributeMaxDynamicSharedMemorySize, SMEM_GEMM);
    cudaFuncSetAttribute(gemm_p<1,3,12>, cudaFuncAttributeMaxDynamicSharedMemorySize, SMEM_GEMM);
    cudaFuncSetAttribute(attn_tc,        cudaFuncAttributeMaxDynamicSharedMemorySize, AT_SMEM_BYTES);

    // 0) weight prep
    pack_w<<<1024, 256>>>((const float4*)Wq, (float4*)wqkv, 0);
    pack_w<<<1024, 256>>>((const float4*)Wk, (float4*)wqkv, 256);
    pack_w<<<1024, 256>>>((const float4*)Wv, (float4*)wqkv, 512);
    round_copy<<<1024, 256>>>((const float4*)Wo, (float4*)wo, DMODEL*DMODEL/4);
    round_copy<<<(3*DMODEL*FF/4 + 255)/256, 256>>>((const float4*)c1w, (float4*)c1, 3*DMODEL*FF/4);
    round_copy<<<(3*FF*DMODEL/4 + 255)/256, 256>>>((const float4*)c2w, (float4*)c2, 3*FF*DMODEL/4);

    // 1) LN1
    ln_kernel<<<ROWS,256>>>(x, ln1g, ln1b, xn);

    // 2) fused QKV projection: [8192,1024] x [1024,3072]
    dim3 gqkv(3*DMODEL/BN, ROWS/BM);   // (12, 64)
    gemm_p<0,0,0><<<gqkv,256,SMEM_GEMM>>>(xn, wqkv, q, nullptr, nullptr,
                                          DMODEL, 3*DMODEL, 0.125f, k, v);

    // 3) attention (tensor-core flash)
    dim3 ga(SEQ/64, BATCH*NH);
    attn_tc<<<ga,128,AT_SMEM_BYTES>>>(mask);

    // 4) output projection + residual
    dim3 go(DMODEL/BN, ROWS/BM);       // (4, 64)
    gemm_p<0,1,0><<<go,256,SMEM_GEMM>>>(ctx, wo, x1, nullptr, x,
                                        DMODEL, DMODEL, 1.0f, nullptr, nullptr);

    // 5) LN2
    ln_kernel<<<ROWS,256>>>(x1, ln2g, ln2b, xn2);

    // 6) conv1
    gemm_p<1,2,10><<<dim3(FF/BN, ROWS/BM),256,SMEM_GEMM>>>(xn2, c1, h1, c1b, nullptr,
                                        3*DMODEL, FF, 1.0f, nullptr, nullptr);

    // 7) conv2 -> final output
    gemm_p<1,3,12><<<dim3(DMODEL/BN, ROWS/BM),256,SMEM_GEMM>>>(h1, c2, out, c2b, x1,
                                        3*FF, DMODEL, 1.0f, nullptr, nullptr);
}

// round 12
// speedup vs baseline: 4.1347x; 1.7283x over previous
#include <cuda_runtime.h>
#include <cuda_fp16.h>
#include <math.h>
#include <stdint.h>

#define BATCH 8
#define SEQ 1024
#define DMODEL 1024
#define NH 16
#define DKH 64
#define FF 4096
#define ROWS (BATCH*SEQ)

// ---------------- scratch (device globals: allocation-free rule) ----------------
__device__ __half g_xn [(size_t)ROWS*DMODEL];     // LN1 out (A of QKV)
__device__ float  g_q  [(size_t)ROWS*DMODEL];     // [B,H,S,DK] fp32 (attention)
__device__ float  g_k  [(size_t)ROWS*DMODEL];
__device__ float  g_v  [(size_t)ROWS*DMODEL];
__device__ __half g_ctx[(size_t)ROWS*DMODEL];     // attn out (A of Wo)
__device__ float  g_x1 [(size_t)ROWS*DMODEL];     // residual after attn
__device__ __half g_xn2[(size_t)ROWS*DMODEL];     // LN2 out (A of conv1)
__device__ __half g_h1 [(size_t)ROWS*FF];         // conv1 out (A of conv2)
// fp16 weights, [N][K] layout
__device__ __half g_wqkvT[(size_t)3*DMODEL*DMODEL];   // rows: q(0..1023)|k|v, K=1024
__device__ __half g_woT  [(size_t)DMODEL*DMODEL];
__device__ __half g_c1T  [(size_t)FF*3*DMODEL];       // [4096][3072]
__device__ __half g_c2T  [(size_t)DMODEL*3*FF];       // [1024][12288]

// ---------------- helpers ----------------
__device__ __forceinline__ float tf32r(float f){
    unsigned u; asm("cvt.rna.tf32.f32 %0, %1;" : "=r"(u) : "f"(f));
    return __uint_as_float(u);
}
__device__ __forceinline__ uint32_t smem_u32(const void* p){
    uint32_t a;
    asm("{ .reg .u64 t; cvta.to.shared.u64 t, %1; cvt.u32.u64 %0, t; }" : "=r"(a) : "l"(p));
    return a;
}
// tf32 m16n8k8 (attention only)
__device__ __forceinline__ void mma8(float* d, const unsigned* a, const unsigned* b){
    asm volatile("mma.sync.aligned.m16n8k8.row.col.f32.tf32.tf32.f32 "
        "{%0,%1,%2,%3},{%4,%5,%6,%7},{%8,%9},{%0,%1,%2,%3};\n"
        : "+f"(d[0]), "+f"(d[1]), "+f"(d[2]), "+f"(d[3])
        : "r"(a[0]), "r"(a[1]), "r"(a[2]), "r"(a[3]), "r"(b[0]), "r"(b[1]));
}
// fp16 m16n8k16 (GEMMs)
__device__ __forceinline__ void mma16(float* d, const unsigned* a, const unsigned* b){
    asm volatile("mma.sync.aligned.m16n8k16.row.col.f32.f16.f16.f32 "
        "{%0,%1,%2,%3},{%4,%5,%6,%7},{%8,%9},{%0,%1,%2,%3};\n"
        : "+f"(d[0]), "+f"(d[1]), "+f"(d[2]), "+f"(d[3])
        : "r"(a[0]), "r"(a[1]), "r"(a[2]), "r"(a[3]), "r"(b[0]), "r"(b[1]));
}
__device__ __forceinline__ void cpa16(uint32_t so, const void* src){
    asm volatile("cp.async.cg.shared.global [%0], [%1], 16, %2;"
                 :: "r"(so), "l"(src), "r"(16));
}

// ---------------- weight prep: fp32 [K][N] -> fp16 [N][K] ----------------
__global__ void __launch_bounds__(256) transpose_h(const float* __restrict__ in,
        __half* __restrict__ out, int K, int N){
    __shared__ float t[32][33];
    int n0 = blockIdx.x*32, k0 = blockIdx.y*32;
    int tx = threadIdx.x, ty = threadIdx.y;
    #pragma unroll
    for (int i=0;i<32;i+=8) t[ty+i][tx] = in[(size_t)(k0+ty+i)*N + n0+tx];
    __syncthreads();
    #pragma unroll
    for (int i=0;i<32;i+=8) out[(size_t)(n0+ty+i)*K + k0+tx] = __float2half_rn(t[tx][ty+i]);
}

// ---------------- LayerNorm (fp16 output: feeds fp16 GEMM A) ----------------
__global__ void __launch_bounds__(256) ln_kernel(const float* __restrict__ x,
        const float* __restrict__ gg, const float* __restrict__ bb, __half* __restrict__ y){
    __shared__ float red[8];
    __shared__ float bc;
    int row = blockIdx.x;
    const float4* xr = (const float4*)(x + (size_t)row*DMODEL);
    float4 v = xr[threadIdx.x];
    float s = v.x+v.y+v.z+v.w;
    #pragma unroll
    for (int o=16;o;o>>=1) s += __shfl_xor_sync(0xffffffffu, s, o);
    if ((threadIdx.x&31)==0) red[threadIdx.x>>5] = s;
    __syncthreads();
    if (threadIdx.x==0){ float t=0; for(int i=0;i<8;i++) t+=red[i]; bc = t*(1.0f/DMODEL); }
    __syncthreads();
    float mu = bc;
    float dx0=v.x-mu, dx1=v.y-mu, dx2=v.z-mu, dx3=v.w-mu;
    float q = dx0*dx0+dx1*dx1+dx2*dx2+dx3*dx3;
    #pragma unroll
    for (int o=16;o;o>>=1) q += __shfl_xor_sync(0xffffffffu, q, o);
    if ((threadIdx.x&31)==0) red[threadIdx.x>>5] = q;
    __syncthreads();
    if (threadIdx.x==0){ float t=0; for(int i=0;i<8;i++) t+=red[i]; bc = rsqrtf(t*(1.0f/DMODEL) + 1e-6f); }
    __syncthreads();
    float rs = bc;
    const float4 g4 = ((const float4*)gg)[threadIdx.x];
    const float4 b4 = ((const float4*)bb)[threadIdx.x];
    __half2* yp = (__half2*)(y + (size_t)row*DMODEL) + 2*threadIdx.x;
    yp[0] = __floats2half2_rn(dx0*rs*g4.x + b4.x, dx1*rs*g4.y + b4.y);
    yp[1] = __floats2half2_rn(dx2*rs*g4.z + b4.z, dx3*rs*g4.w + b4.w);
}

// ---------------- pipelined FP16 mma GEMM: 128M x 256N, BK=64, 3-stage ----------------
// A fp16 [M][K]; B fp16 [N][K] (K-major). 8 warps 2(M)x4(N), warp tile 64x64.
// smem stride 72 halves -> fragment bank = 4g+tg+const: conflict-free.
#define BM 128
#define BN 256
#define BK 64
#define AH (BK+8)                       // 72 halves
#define ABYTES (BM*AH*2)                // 18432
#define BBYTES (BN*AH*2)                // 36864
#define STAGEB (ABYTES+BBYTES)          // 55296
#define NSTAGE 3
#define SMEM_GEMM (NSTAGE*STAGEB)       // 165888

template<int AMODE,int CSH>
__device__ __forceinline__ void load_chunk(const __half* __restrict__ A,
        const __half* __restrict__ BT, int Kd, int bm, int bn, int c,
        uint32_t smem_base, int tid){
    const int k0 = c*BK;
    const uint32_t st = smem_base + (uint32_t)(c % NSTAGE)*STAGEB;
    // A tile: 128 rows x 8 segs(16B=8 halves) = 1024, 4/thread
    #pragma unroll
    for (int i=0;i<4;i++){
        int idx = i*256 + tid;
        int row = idx>>3, seg = idx&7;
        uint32_t so = st + (uint32_t)(row*(AH*2) + seg*16);
        const __half* src; int sz = 16;
        if (AMODE==0){
            src = A + (size_t)(bm+row)*Kd + k0 + seg*8;
        } else {
            int m = bm+row, b = m>>10, s = m&1023;
            int kw = k0 >> CSH;
            int cin = (k0 & ((1<<CSH)-1)) + seg*8;
            int ss = s + kw - 1;
            src = A + (((size_t)((b<<10)+ss)) << CSH) + cin;
            if ((unsigned)ss >= 1024u) sz = 0;
        }
        asm volatile("cp.async.cg.shared.global [%0], [%1], 16, %2;"
                     :: "r"(so), "l"(src), "r"(sz));
    }
    // B tile: 256 rows x 8 segs = 2048, 8/thread
    #pragma unroll
    for (int i=0;i<8;i++){
        int idx = i*256 + tid;
        int row = idx>>3, seg = idx&7;
        uint32_t so = st + (uint32_t)ABYTES + (uint32_t)(row*(AH*2) + seg*16);
        const __half* src = BT + (size_t)(bn+row)*Kd + k0 + seg*8;
        asm volatile("cp.async.cg.shared.global [%0], [%1], 16, %2;"
                     :: "r"(so), "l"(src), "r"(16));
    }
    asm volatile("cp.async.commit_group;" ::: "memory");
}

// EPI: 0 = qkv scatter fp32 (q scaled, tf32-rounded); 1 = fp32 res+acc;
//      2 = fp16 relu(acc+bias); 3 = fp32 res+relu(acc+bias)
template<int AMODE,int EPI,int CSH>
__global__ void __launch_bounds__(256,1)
gemm_h(const __half* __restrict__ A, const __half* __restrict__ BT,
       void* __restrict__ Cv, const float* __restrict__ bias,
       const float* __restrict__ res, int Kd, int N, float scale,
       float* __restrict__ Kp, float* __restrict__ Vp)
{
    extern __shared__ __align__(16) char smem[];
    uint32_t smem_base = smem_u32(smem);
    const int tid = threadIdx.x;
    const int bm = blockIdx.y*BM, bn = blockIdx.x*BN;
    const int warp = tid>>5, lane = tid&31;
    const int wm = (warp&1)*64, wn = (warp>>1)*64;
    const int g = lane>>2, tg = lane&3;
    const int NC = Kd/BK;

    float acc[4][8][4];
    #pragma unroll
    for (int i=0;i<4;i++)
        #pragma unroll
        for (int j=0;j<8;j++)
            #pragma unroll
            for (int e=0;e<4;e++) acc[i][j][e]=0.f;

    load_chunk<AMODE,CSH>(A,BT,Kd,bm,bn,0,smem_base,tid);
    load_chunk<AMODE,CSH>(A,BT,Kd,bm,bn,1,smem_base,tid);

    for (int c=0;c<NC;c++){
        if (c < NC-1){ asm volatile("cp.async.wait_group 1;" ::: "memory"); }
        else         { asm volatile("cp.async.wait_group 0;" ::: "memory"); }
        __syncthreads();
        if (c+2 < NC) load_chunk<AMODE,CSH>(A,BT,Kd,bm,bn,c+2,smem_base,tid);
        const __half* sA = (const __half*)(smem + (size_t)(c%NSTAGE)*STAGEB);
        const __half* sB = (const __half*)(smem + (size_t)(c%NSTAGE)*STAGEB + ABYTES);
        #pragma unroll
        for (int ks=0;ks<4;ks++){
            int kb = ks*16;
            unsigned bfr[8][2];
            #pragma unroll
            for (int nb=0;nb<8;nb++){
                int n = wn + nb*8 + g;
                bfr[nb][0] = *(const unsigned*)(sB + n*AH + kb + 2*tg);
                bfr[nb][1] = *(const unsigned*)(sB + n*AH + kb + 2*tg + 8);
            }
            #pragma unroll
            for (int im=0;im<4;im++){
                int m = wm + im*16;
                unsigned afr[4];
                afr[0] = *(const unsigned*)(sA + (m+g  )*AH + kb + 2*tg);
                afr[1] = *(const unsigned*)(sA + (m+g+8)*AH + kb + 2*tg);
                afr[2] = *(const unsigned*)(sA + (m+g  )*AH + kb + 2*tg + 8);
                afr[3] = *(const unsigned*)(sA + (m+g+8)*AH + kb + 2*tg + 8);
                #pragma unroll
                for (int nb=0;nb<8;nb++)
                    mma16(acc[im][nb], afr, bfr[nb]);
            }
        }
        __syncthreads();
    }

    // ---- epilogue ----
    if (EPI==0){
        const int which = bn >> 10;                 // 0=q 1=k 2=v
        float* dst = (which==0) ? (float*)Cv : (which==1 ? Kp : Vp);
        const float sc = (which==0) ? scale : 1.0f;
        #pragma unroll
        for (int im=0;im<4;im++){
            #pragma unroll
            for (int eh=0;eh<2;eh++){
                int row = bm + wm + im*16 + g + eh*8;
                int b = row>>10, s = row&1023;
                #pragma unroll
                for (int nb=0;nb<8;nb++){
                    int col = (bn & 1023) + wn + nb*8 + 2*tg;
                    int h = col>>6, dk = col&63;
                    float2 o;
                    o.x = tf32r(acc[im][nb][eh*2  ]*sc);
                    o.y = tf32r(acc[im][nb][eh*2+1]*sc);
                    *(float2*)(dst + (((size_t)((b<<4)+h)<<10) + s)*DKH + dk) = o;
                }
            }
        }
    } else if (EPI==2){
        __half* C = (__half*)Cv;
        #pragma unroll
        for (int im=0;im<4;im++){
            #pragma unroll
            for (int eh=0;eh<2;eh++){
                int row = bm + wm + im*16 + g + eh*8;
                #pragma unroll
                for (int nb=0;nb<8;nb++){
                    int col = bn + wn + nb*8 + 2*tg;
                    size_t idx = (size_t)row*N + col;
                    float ox = fmaxf(acc[im][nb][eh*2  ] + __ldg(bias+col  ), 0.f);
                    float oy = fmaxf(acc[im][nb][eh*2+1] + __ldg(bias+col+1), 0.f);
                    *(__half2*)(C + idx) = __floats2half2_rn(ox, oy);
                }
            }
        }
    } else {
        float* C = (float*)Cv;
        #pragma unroll
        for (int im=0;im<4;im++){
            #pragma unroll
            for (int eh=0;eh<2;eh++){
                int row = bm + wm + im*16 + g + eh*8;
                #pragma unroll
                for (int nb=0;nb<8;nb++){
                    int col = bn + wn + nb*8 + 2*tg;
                    size_t idx = (size_t)row*N + col;
                    float2 o;
                    o.x = acc[im][nb][eh*2  ];
                    o.y = acc[im][nb][eh*2+1];
                    if (EPI==3){
                        o.x = fmaxf(o.x + __ldg(bias+col  ), 0.f);
                        o.y = fmaxf(o.y + __ldg(bias+col+1), 0.f);
                    }
                    float2 rv = *(const float2*)(res + idx);
                    o.x += rv.x; o.y += rv.y;
                    *(float2*)(C + idx) = o;
                }
            }
        }
    }
}

// ---------------- tensor-core flash attention (tf32; fp16 ctx output) ----------------
#define AT_STR 68
#define AT_KTILE (64*AT_STR)
#define AT_SMEM_FLOATS (5*AT_KTILE + 4*16*AT_STR)
#define AT_SMEM_BYTES (AT_SMEM_FLOATS*4)

__global__ void __launch_bounds__(128,2) attn_tc(const int* __restrict__ mask){
    extern __shared__ __align__(16) float af[];
    float* sK  = af;
    float* sVr = af + 2*AT_KTILE;
    float* sVT = af + 4*AT_KTILE;
    float* sP  = af + 5*AT_KTILE;
    __shared__ int sM[2][64];

    const int tid = threadIdx.x;
    const int wq = tid>>5, lane = tid&31;
    const int g = lane>>2, tg = lane&3;
    const int bh = blockIdx.y;
    const int b = bh>>4, h = bh&15;
    const int qb = blockIdx.x*64;

    const float* kbase = g_k + ((size_t)bh<<10)*DKH;
    const float* vbase = g_v + ((size_t)bh<<10)*DKH;
    const int*   mbase = mask + (b<<10);
    const uint32_t sKu  = smem_u32(sK);
    const uint32_t sVru = smem_u32(sVr);

    unsigned qf[8][4];
    {
        const float* q0 = g_q + (((size_t)bh<<10) + qb + wq*16 + g)*DKH;
        const float* q1 = q0 + 8*DKH;
        #pragma unroll
        for (int k8=0;k8<8;k8++){
            qf[k8][0] = __float_as_uint(q0[k8*8+tg]);
            qf[k8][1] = __float_as_uint(q1[k8*8+tg]);
            qf[k8][2] = __float_as_uint(q0[k8*8+tg+4]);
            qf[k8][3] = __float_as_uint(q1[k8*8+tg+4]);
        }
    }
    #pragma unroll
    for (int i=0;i<8;i++){
        int idx = i*128 + tid;
        int r = idx>>4, c4 = idx&15;
        cpa16(sKu  + (uint32_t)(r*AT_STR + c4*4)*4u, kbase + (size_t)r*DKH + c4*4);
        cpa16(sVru + (uint32_t)(r*AT_STR + c4*4)*4u, vbase + (size_t)r*DKH + c4*4);
    }
    asm volatile("cp.async.commit_group;" ::: "memory");
    if (tid < 64) sM[0][tid] = mbase[tid];
    asm volatile("cp.async.wait_group 0;" ::: "memory");
    __syncthreads();

    float oA[8][4];
    #pragma unroll
    for (int nb=0;nb<8;nb++){ oA[nb][0]=0.f; oA[nb][1]=0.f; oA[nb][2]=0.f; oA[nb][3]=0.f; }
    float mr0 = -1e30f, mr1 = -1e30f, l0 = 0.f, l1 = 0.f;
    float* sPw = sP + wq*16*AT_STR;

    for (int kt=0;kt<16;kt++){
        const int st = kt & 1;
        if (kt < 15){
            const float* kn = kbase + (size_t)(kt+1)*64*DKH;
            const float* vn = vbase + (size_t)(kt+1)*64*DKH;
            uint32_t dK = sKu  + (uint32_t)(st^1)*AT_KTILE*4u;
            uint32_t dV = sVru + (uint32_t)(st^1)*AT_KTILE*4u;
            #pragma unroll
            for (int i=0;i<8;i++){
                int idx = i*128 + tid;
                int r = idx>>4, c4 = idx&15;
                cpa16(dK + (uint32_t)(r*AT_STR + c4*4)*4u, kn + (size_t)r*DKH + c4*4);
                cpa16(dV + (uint32_t)(r*AT_STR + c4*4)*4u, vn + (size_t)r*DKH + c4*4);
            }
            asm volatile("cp.async.commit_group;" ::: "memory");
        }
        float s[8][4];
        #pragma unroll
        for (int nb=0;nb<8;nb++){ s[nb][0]=0.f; s[nb][1]=0.f; s[nb][2]=0.f; s[nb][3]=0.f; }
        const float* sKs = sK + st*AT_KTILE;
        #pragma unroll
        for (int k8=0;k8<8;k8++){
            unsigned bfr[8][2];
            #pragma unroll
            for (int nb=0;nb<8;nb++){
                bfr[nb][0] = __float_as_uint(sKs[(nb*8+g)*AT_STR + k8*8+tg  ]);
                bfr[nb][1] = __float_as_uint(sKs[(nb*8+g)*AT_STR + k8*8+tg+4]);
            }
            #pragma unroll
            for (int nb=0;nb<8;nb++) mma8(s[nb], qf[k8], bfr[nb]);
        }
        float rmax0 = -1e30f, rmax1 = -1e30f;
        #pragma unroll
        for (int nb=0;nb<8;nb++){
            int c0 = nb*8 + 2*tg;
            if (sM[st][c0  ]){ s[nb][0] = -1e30f; s[nb][2] = -1e30f; }
            if (sM[st][c0+1]){ s[nb][1] = -1e30f; s[nb][3] = -1e30f; }
            rmax0 = fmaxf(rmax0, fmaxf(s[nb][0], s[nb][1]));
            rmax1 = fmaxf(rmax1, fmaxf(s[nb][2], s[nb][3]));
        }
        rmax0 = fmaxf(rmax0, __shfl_xor_sync(0xffffffffu, rmax0, 1));
        rmax0 = fmaxf(rmax0, __shfl_xor_sync(0xffffffffu, rmax0, 2));
        rmax1 = fmaxf(rmax1, __shfl_xor_sync(0xffffffffu, rmax1, 1));
        rmax1 = fmaxf(rmax1, __shfl_xor_sync(0xffffffffu, rmax1, 2));
        float nm0 = fmaxf(mr0, rmax0), nm1 = fmaxf(mr1, rmax1);
        float corr0 = __expf(mr0 - nm0), corr1 = __expf(mr1 - nm1);
        mr0 = nm0; mr1 = nm1;
        float sum0 = 0.f, sum1 = 0.f;
        #pragma unroll
        for (int nb=0;nb<8;nb++){
            float p0 = __expf(s[nb][0]-nm0), p1 = __expf(s[nb][1]-nm0);
            float p2 = __expf(s[nb][2]-nm1), p3 = __expf(s[nb][3]-nm1);
            sum0 += p0+p1; sum1 += p2+p3;
            *(float2*)(sPw + (g  )*AT_STR + nb*8 + 2*tg) = make_float2(tf32r(p0), tf32r(p1));
            *(float2*)(sPw + (g+8)*AT_STR + nb*8 + 2*tg) = make_float2(tf32r(p2), tf32r(p3));
        }
        sum0 += __shfl_xor_sync(0xffffffffu, sum0, 1);
        sum0 += __shfl_xor_sync(0xffffffffu, sum0, 2);
        sum1 += __shfl_xor_sync(0xffffffffu, sum1, 1);
        sum1 += __shfl_xor_sync(0xffffffffu, sum1, 2);
        l0 = l0*corr0 + sum0;
        l1 = l1*corr1 + sum1;
        #pragma unroll
        for (int nb=0;nb<8;nb++){
            oA[nb][0]*=corr0; oA[nb][1]*=corr0; oA[nb][2]*=corr1; oA[nb][3]*=corr1;
        }
        __syncthreads();
        {
            const float* vs = sVr + st*AT_KTILE;
            #pragma unroll
            for (int i=0;i<8;i++){
                int idx = i*128 + tid;
                int c4 = idx>>6, r = idx&63;
                float4 vv = *(const float4*)(vs + r*AT_STR + c4*4);
                sVT[(c4*4  )*AT_STR + r] = vv.x;
                sVT[(c4*4+1)*AT_STR + r] = vv.y;
                sVT[(c4*4+2)*AT_STR + r] = vv.z;
                sVT[(c4*4+3)*AT_STR + r] = vv.w;
            }
            if (kt < 15 && tid < 64) sM[st^1][tid] = mbase[(kt+1)*64 + tid];
        }
        __syncthreads();
        #pragma unroll
        for (int k8=0;k8<8;k8++){
            unsigned afr[4], bfr[8][2];
            afr[0] = __float_as_uint(sPw[(g  )*AT_STR + k8*8+tg  ]);
            afr[1] = __float_as_uint(sPw[(g+8)*AT_STR + k8*8+tg  ]);
            afr[2] = __float_as_uint(sPw[(g  )*AT_STR + k8*8+tg+4]);
            afr[3] = __float_as_uint(sPw[(g+8)*AT_STR + k8*8+tg+4]);
            #pragma unroll
            for (int nb=0;nb<8;nb++){
                bfr[nb][0] = __float_as_uint(sVT[(nb*8+g)*AT_STR + k8*8+tg  ]);
                bfr[nb][1] = __float_as_uint(sVT[(nb*8+g)*AT_STR + k8*8+tg+4]);
            }
            #pragma unroll
            for (int nb=0;nb<8;nb++) mma8(oA[nb], afr, bfr[nb]);
        }
        asm volatile("cp.async.wait_group 0;" ::: "memory");
        __syncthreads();
    }
    float inv0 = 1.f/l0, inv1 = 1.f/l1;
    int s0 = qb + wq*16 + g;
    __half* out0 = g_ctx + (((size_t)(b<<10)) + s0)*DMODEL + h*DKH;
    __half* out1 = out0 + 8*DMODEL;
    #pragma unroll
    for (int nb=0;nb<8;nb++){
        int c0 = nb*8 + 2*tg;
        *(__half2*)(out0 + c0) = __floats2half2_rn(oA[nb][0]*inv0, oA[nb][1]*inv0);
        *(__half2*)(out1 + c0) = __floats2half2_rn(oA[nb][2]*inv1, oA[nb][3]*inv1);
    }
}

// ---------------- launch ----------------
extern "C" void kernel_launch(void* const* d_in, const int* in_sizes, int n_in,
                              void* d_out, int out_size){
    const float* x    = (const float*)d_in[0];
    const int*   mask = (const int*)  d_in[1];
    const float* Wq   = (const float*)d_in[2];
    const float* Wk   = (const float*)d_in[3];
    const float* Wv   = (const float*)d_in[4];
    const float* Wo   = (const float*)d_in[5];
    const float* ln1g = (const float*)d_in[6];
    const float* ln1b = (const float*)d_in[7];
    const float* ln2g = (const float*)d_in[8];
    const float* ln2b = (const float*)d_in[9];
    const float* c1w  = (const float*)d_in[10];
    const float* c1b  = (const float*)d_in[11];
    const float* c2w  = (const float*)d_in[12];
    const float* c2b  = (const float*)d_in[13];
    float* out = (float*)d_out;

    __half *xn, *ctx, *xn2, *h1, *wqkvT, *woT, *c1T, *c2T;
    float *q, *k, *v, *x1;
    cudaGetSymbolAddress((void**)&xn,   g_xn);
    cudaGetSymbolAddress((void**)&q,    g_q);
    cudaGetSymbolAddress((void**)&k,    g_k);
    cudaGetSymbolAddress((void**)&v,    g_v);
    cudaGetSymbolAddress((void**)&ctx,  g_ctx);
    cudaGetSymbolAddress((void**)&x1,   g_x1);
    cudaGetSymbolAddress((void**)&xn2,  g_xn2);
    cudaGetSymbolAddress((void**)&h1,   g_h1);
    cudaGetSymbolAddress((void**)&wqkvT,g_wqkvT);
    cudaGetSymbolAddress((void**)&woT,  g_woT);
    cudaGetSymbolAddress((void**)&c1T,  g_c1T);
    cudaGetSymbolAddress((void**)&c2T,  g_c2T);

    cudaFuncSetAttribute(gemm_h<0,0,0>,  cudaFuncAttributeMaxDynamicSharedMemorySize, SMEM_GEMM);
    cudaFuncSetAttribute(gemm_h<0,1,0>,  cudaFuncAttributeMaxDynamicSharedMemorySize, SMEM_GEMM);
    cudaFuncSetAttribute(gemm_h<1,2,10>, cudaFuncAttributeMaxDynamicSharedMemorySize, SMEM_GEMM);
    cudaFuncSetAttribute(gemm_h<1,3,12>, cudaFuncAttributeMaxDynamicSharedMemorySize, SMEM_GEMM);
    cudaFuncSetAttribute(attn_tc,        cudaFuncAttributeMaxDynamicSharedMemorySize, AT_SMEM_BYTES);

    // 0) weight prep: transpose + fp16 convert ([K][N] -> [N][K])
    dim3 tb(32,8);
    transpose_h<<<dim3(32,32), tb>>>(Wq, wqkvT,               DMODEL, DMODEL);
    transpose_h<<<dim3(32,32), tb>>>(Wk, wqkvT + (size_t)1024*DMODEL, DMODEL, DMODEL);
    transpose_h<<<dim3(32,32), tb>>>(Wv, wqkvT + (size_t)2048*DMODEL, DMODEL, DMODEL);
    transpose_h<<<dim3(32,32), tb>>>(Wo, woT, DMODEL, DMODEL);
    transpose_h<<<dim3(FF/32, 3*DMODEL/32), tb>>>(c1w, c1T, 3*DMODEL, FF);
    transpose_h<<<dim3(DMODEL/32, 3*FF/32), tb>>>(c2w, c2T, 3*FF, DMODEL);

    // 1) LN1 (fp16 out)
    ln_kernel<<<ROWS,256>>>(x, ln1g, ln1b, xn);

    // 2) fused QKV projection: [8192,1024] x [3072,1024]^T -> q/k/v fp32
    dim3 gqkv(3*DMODEL/BN, ROWS/BM);   // (12, 64)
    gemm_h<0,0,0><<<gqkv,256,SMEM_GEMM>>>(xn, wqkvT, q, nullptr, nullptr,
                                          DMODEL, 3*DMODEL, 0.125f, k, v);

    // 3) attention (tf32 flash; fp16 ctx out)
    dim3 ga(SEQ/64, BATCH*NH);
    attn_tc<<<ga,128,AT_SMEM_BYTES>>>(mask);

    // 4) output projection + residual (fp32 x1)
    dim3 go(DMODEL/BN, ROWS/BM);       // (4, 64)
    gemm_h<0,1,0><<<go,256,SMEM_GEMM>>>(ctx, woT, x1, nullptr, x,
                                        DMODEL, DMODEL, 1.0f, nullptr, nullptr);

    // 5) LN2 (fp16 out)
    ln_kernel<<<ROWS,256>>>(x1, ln2g, ln2b, xn2);

    // 6) conv1 (im2col, CIN=1024) + bias + ReLU -> fp16 h1
    gemm_h<1,2,10><<<dim3(FF/BN, ROWS/BM),256,SMEM_GEMM>>>(xn2, c1T, h1, c1b, nullptr,
                                        3*DMODEL, FF, 1.0f, nullptr, nullptr);

    // 7) conv2 (im2col, CIN=4096) + bias + ReLU + residual -> fp32 out
    gemm_h<1,3,12><<<dim3(DMODEL/BN, ROWS/BM),256,SMEM_GEMM>>>(h1, c2T, out, c2b, x1,
                                        3*FF, DMODEL, 1.0f, nullptr, nullptr);
}

// round 17
// speedup vs baseline: 4.3691x; 1.0567x over previous
#include <cuda_runtime.h>
#include <cuda_fp16.h>
#include <math.h>
#include <stdint.h>

#define BATCH 8
#define SEQ 1024
#define DMODEL 1024
#define NH 16
#define DKH 64
#define FF 4096
#define ROWS (BATCH*SEQ)

// ---------------- scratch (device globals: allocation-free rule) ----------------
__device__ __half g_xn [(size_t)ROWS*DMODEL];     // LN1 out (A of QKV)
__device__ __half g_q  [(size_t)ROWS*DMODEL];     // [B,H,S,DK] fp16
__device__ __half g_k  [(size_t)ROWS*DMODEL];
__device__ __half g_v  [(size_t)ROWS*DMODEL];
__device__ __half g_ctx[(size_t)ROWS*DMODEL];     // attn out (A of Wo)
__device__ float  g_x1 [(size_t)ROWS*DMODEL];     // residual after attn
__device__ __half g_xn2[(size_t)ROWS*DMODEL];     // LN2 out (A of conv1)
__device__ __half g_h1 [(size_t)ROWS*FF];         // conv1 out (A of conv2)
// fp16 weights, [N][K] layout
__device__ __half g_wqkvT[(size_t)3*DMODEL*DMODEL];   // rows: q|k|v, K=1024
__device__ __half g_woT  [(size_t)DMODEL*DMODEL];
__device__ __half g_c1T  [(size_t)FF*3*DMODEL];       // [4096][3072]
__device__ __half g_c2T  [(size_t)DMODEL*3*FF];       // [1024][12288]

// ---------------- helpers ----------------
__device__ __forceinline__ uint32_t smem_u32(const void* p){
    uint32_t a;
    asm("{ .reg .u64 t; cvta.to.shared.u64 t, %1; cvt.u32.u64 %0, t; }" : "=r"(a) : "l"(p));
    return a;
}
// fp16 m16n8k16
__device__ __forceinline__ void mma16(float* d, const unsigned* a, const unsigned* b){
    asm volatile("mma.sync.aligned.m16n8k16.row.col.f32.f16.f16.f32 "
        "{%0,%1,%2,%3},{%4,%5,%6,%7},{%8,%9},{%0,%1,%2,%3};\n"
        : "+f"(d[0]), "+f"(d[1]), "+f"(d[2]), "+f"(d[3])
        : "r"(a[0]), "r"(a[1]), "r"(a[2]), "r"(a[3]), "r"(b[0]), "r"(b[1]));
}
__device__ __forceinline__ void cpa16(uint32_t so, const void* src){
    asm volatile("cp.async.cg.shared.global [%0], [%1], 16, %2;"
                 :: "r"(so), "l"(src), "r"(16));
}

// ---------------- weight prep: fp32 [K][N] -> fp16 [N][K] ----------------
__global__ void __launch_bounds__(256) transpose_h(const float* __restrict__ in,
        __half* __restrict__ out, int K, int N){
    __shared__ float t[32][33];
    int n0 = blockIdx.x*32, k0 = blockIdx.y*32;
    int tx = threadIdx.x, ty = threadIdx.y;
    #pragma unroll
    for (int i=0;i<32;i+=8) t[ty+i][tx] = in[(size_t)(k0+ty+i)*N + n0+tx];
    __syncthreads();
    #pragma unroll
    for (int i=0;i<32;i+=8) out[(size_t)(n0+ty+i)*K + k0+tx] = __float2half_rn(t[tx][ty+i]);
}

// ---------------- LayerNorm (fp16 output) ----------------
__global__ void __launch_bounds__(256) ln_kernel(const float* __restrict__ x,
        const float* __restrict__ gg, const float* __restrict__ bb, __half* __restrict__ y){
    __shared__ float red[8];
    __shared__ float bc;
    int row = blockIdx.x;
    const float4* xr = (const float4*)(x + (size_t)row*DMODEL);
    float4 v = xr[threadIdx.x];
    float s = v.x+v.y+v.z+v.w;
    #pragma unroll
    for (int o=16;o;o>>=1) s += __shfl_xor_sync(0xffffffffu, s, o);
    if ((threadIdx.x&31)==0) red[threadIdx.x>>5] = s;
    __syncthreads();
    if (threadIdx.x==0){ float t=0; for(int i=0;i<8;i++) t+=red[i]; bc = t*(1.0f/DMODEL); }
    __syncthreads();
    float mu = bc;
    float dx0=v.x-mu, dx1=v.y-mu, dx2=v.z-mu, dx3=v.w-mu;
    float q = dx0*dx0+dx1*dx1+dx2*dx2+dx3*dx3;
    #pragma unroll
    for (int o=16;o;o>>=1) q += __shfl_xor_sync(0xffffffffu, q, o);
    if ((threadIdx.x&31)==0) red[threadIdx.x>>5] = q;
    __syncthreads();
    if (threadIdx.x==0){ float t=0; for(int i=0;i<8;i++) t+=red[i]; bc = rsqrtf(t*(1.0f/DMODEL) + 1e-6f); }
    __syncthreads();
    float rs = bc;
    const float4 g4 = ((const float4*)gg)[threadIdx.x];
    const float4 b4 = ((const float4*)bb)[threadIdx.x];
    __half2* yp = (__half2*)(y + (size_t)row*DMODEL) + 2*threadIdx.x;
    yp[0] = __floats2half2_rn(dx0*rs*g4.x + b4.x, dx1*rs*g4.y + b4.y);
    yp[1] = __floats2half2_rn(dx2*rs*g4.z + b4.z, dx3*rs*g4.w + b4.w);
}

// ---------------- pipelined FP16 mma GEMM: 128M x 256N, BK=64, 3-stage ----------------
#define BM 128
#define BN 256
#define BK 64
#define AH (BK+8)                       // 72 halves
#define ABYTES (BM*AH*2)                // 18432
#define BBYTES (BN*AH*2)                // 36864
#define STAGEB (ABYTES+BBYTES)          // 55296
#define NSTAGE 3
#define SMEM_GEMM (NSTAGE*STAGEB)       // 165888

template<int AMODE,int CSH>
__device__ __forceinline__ void load_chunk(const __half* __restrict__ A,
        const __half* __restrict__ BT, int Kd, int bm, int bn, int c,
        uint32_t smem_base, int tid){
    const int k0 = c*BK;
    const uint32_t st = smem_base + (uint32_t)(c % NSTAGE)*STAGEB;
    #pragma unroll
    for (int i=0;i<4;i++){
        int idx = i*256 + tid;
        int row = idx>>3, seg = idx&7;
        uint32_t so = st + (uint32_t)(row*(AH*2) + seg*16);
        const __half* src; int sz = 16;
        if (AMODE==0){
            src = A + (size_t)(bm+row)*Kd + k0 + seg*8;
        } else {
            int m = bm+row, b = m>>10, s = m&1023;
            int kw = k0 >> CSH;
            int cin = (k0 & ((1<<CSH)-1)) + seg*8;
            int ss = s + kw - 1;
            src = A + (((size_t)((b<<10)+ss)) << CSH) + cin;
            if ((unsigned)ss >= 1024u) sz = 0;
        }
        asm volatile("cp.async.cg.shared.global [%0], [%1], 16, %2;"
                     :: "r"(so), "l"(src), "r"(sz));
    }
    #pragma unroll
    for (int i=0;i<8;i++){
        int idx = i*256 + tid;
        int row = idx>>3, seg = idx&7;
        uint32_t so = st + (uint32_t)ABYTES + (uint32_t)(row*(AH*2) + seg*16);
        const __half* src = BT + (size_t)(bn+row)*Kd + k0 + seg*8;
        asm volatile("cp.async.cg.shared.global [%0], [%1], 16, %2;"
                     :: "r"(so), "l"(src), "r"(16));
    }
    asm volatile("cp.async.commit_group;" ::: "memory");
}

// EPI: 0 = qkv scatter fp16 (q scaled); 1 = fp32 res+acc;
//      2 = fp16 relu(acc+bias); 3 = fp32 res+relu(acc+bias)
template<int AMODE,int EPI,int CSH>
__global__ void __launch_bounds__(256,1)
gemm_h(const __half* __restrict__ A, const __half* __restrict__ BT,
       void* __restrict__ Cv, const float* __restrict__ bias,
       const float* __restrict__ res, int Kd, int N, float scale,
       __half* __restrict__ Kp, __half* __restrict__ Vp)
{
    extern __shared__ __align__(16) char smem[];
    uint32_t smem_base = smem_u32(smem);
    const int tid = threadIdx.x;
    const int bm = blockIdx.y*BM, bn = blockIdx.x*BN;
    const int warp = tid>>5, lane = tid&31;
    const int wm = (warp&1)*64, wn = (warp>>1)*64;
    const int g = lane>>2, tg = lane&3;
    const int NC = Kd/BK;

    float acc[4][8][4];
    #pragma unroll
    for (int i=0;i<4;i++)
        #pragma unroll
        for (int j=0;j<8;j++)
            #pragma unroll
            for (int e=0;e<4;e++) acc[i][j][e]=0.f;

    load_chunk<AMODE,CSH>(A,BT,Kd,bm,bn,0,smem_base,tid);
    load_chunk<AMODE,CSH>(A,BT,Kd,bm,bn,1,smem_base,tid);

    for (int c=0;c<NC;c++){
        if (c < NC-1){ asm volatile("cp.async.wait_group 1;" ::: "memory"); }
        else         { asm volatile("cp.async.wait_group 0;" ::: "memory"); }
        __syncthreads();
        if (c+2 < NC) load_chunk<AMODE,CSH>(A,BT,Kd,bm,bn,c+2,smem_base,tid);
        const __half* sA = (const __half*)(smem + (size_t)(c%NSTAGE)*STAGEB);
        const __half* sB = (const __half*)(smem + (size_t)(c%NSTAGE)*STAGEB + ABYTES);
        #pragma unroll
        for (int ks=0;ks<4;ks++){
            int kb = ks*16;
            unsigned bfr[8][2];
            #pragma unroll
            for (int nb=0;nb<8;nb++){
                int n = wn + nb*8 + g;
                bfr[nb][0] = *(const unsigned*)(sB + n*AH + kb + 2*tg);
                bfr[nb][1] = *(const unsigned*)(sB + n*AH + kb + 2*tg + 8);
            }
            #pragma unroll
            for (int im=0;im<4;im++){
                int m = wm + im*16;
                unsigned afr[4];
                afr[0] = *(const unsigned*)(sA + (m+g  )*AH + kb + 2*tg);
                afr[1] = *(const unsigned*)(sA + (m+g+8)*AH + kb + 2*tg);
                afr[2] = *(const unsigned*)(sA + (m+g  )*AH + kb + 2*tg + 8);
                afr[3] = *(const unsigned*)(sA + (m+g+8)*AH + kb + 2*tg + 8);
                #pragma unroll
                for (int nb=0;nb<8;nb++)
                    mma16(acc[im][nb], afr, bfr[nb]);
            }
        }
        __syncthreads();
    }

    // ---- epilogue ----
    if (EPI==0){
        const int which = bn >> 10;                 // 0=q 1=k 2=v
        __half* dst = (which==0) ? (__half*)Cv : (which==1 ? Kp : Vp);
        const float sc = (which==0) ? scale : 1.0f;
        #pragma unroll
        for (int im=0;im<4;im++){
            #pragma unroll
            for (int eh=0;eh<2;eh++){
                int row = bm + wm + im*16 + g + eh*8;
                int b = row>>10, s = row&1023;
                #pragma unroll
                for (int nb=0;nb<8;nb++){
                    int col = (bn & 1023) + wn + nb*8 + 2*tg;
                    int h = col>>6, dk = col&63;
                    *(__half2*)(dst + (((size_t)((b<<4)+h)<<10) + s)*DKH + dk) =
                        __floats2half2_rn(acc[im][nb][eh*2]*sc, acc[im][nb][eh*2+1]*sc);
                }
            }
        }
    } else if (EPI==2){
        __half* C = (__half*)Cv;
        #pragma unroll
        for (int im=0;im<4;im++){
            #pragma unroll
            for (int eh=0;eh<2;eh++){
                int row = bm + wm + im*16 + g + eh*8;
                #pragma unroll
                for (int nb=0;nb<8;nb++){
                    int col = bn + wn + nb*8 + 2*tg;
                    size_t idx = (size_t)row*N + col;
                    float ox = fmaxf(acc[im][nb][eh*2  ] + __ldg(bias+col  ), 0.f);
                    float oy = fmaxf(acc[im][nb][eh*2+1] + __ldg(bias+col+1), 0.f);
                    *(__half2*)(C + idx) = __floats2half2_rn(ox, oy);
                }
            }
        }
    } else {
        float* C = (float*)Cv;
        #pragma unroll
        for (int im=0;im<4;im++){
            #pragma unroll
            for (int eh=0;eh<2;eh++){
                int row = bm + wm + im*16 + g + eh*8;
                #pragma unroll
                for (int nb=0;nb<8;nb++){
                    int col = bn + wn + nb*8 + 2*tg;
                    size_t idx = (size_t)row*N + col;
                    float2 o;
                    o.x = acc[im][nb][eh*2  ];
                    o.y = acc[im][nb][eh*2+1];
                    if (EPI==3){
                        o.x = fmaxf(o.x + __ldg(bias+col  ), 0.f);
                        o.y = fmaxf(o.y + __ldg(bias+col+1), 0.f);
                    }
                    float2 rv = *(const float2*)(res + idx);
                    o.x += rv.x; o.y += rv.y;
                    *(float2*)(C + idx) = o;
                }
            }
        }
    }
}

// ---------------- fp16 tensor-core flash attention ----------------
// CTA: 64 q rows x one (b,h); 4 warps (warp = m16). KV tiles 64, double-buffered.
// AT_H = 88 halves -> 176-byte rows (every cp.async dst 16B-aligned); 44 words
// % 32 == 12 -> fragment LDS bank = 12g + tg + const, perfect permutation.
// R15 BUG FIX: K/V rows are 128 B = 8 x 16B segs; loader now covers ALL 8 segs
// (R13/R15 loaded only segs 0-3, leaving the upper 32 halves of every row
// uninitialized -> NaN).
#define AT_H 88
#define AT_TILEH (64*AT_H)               // 5632 halves per tile
#define AT_SMEM_BYTES (6*AT_TILEH*2)     // sK[2] sVr[2] sVT sP -> 67584 B

__global__ void __launch_bounds__(128,2) attn_tc(const int* __restrict__ mask){
    extern __shared__ __align__(16) __half ah[];
    __half* sK  = ah;                     // 2 stages
    __half* sVr = ah + 2*AT_TILEH;        // 2 stages
    __half* sVT = ah + 4*AT_TILEH;
    __half* sP  = ah + 5*AT_TILEH;        // 4 warps x 16 x AT_H
    __shared__ int sM[2][64];

    const int tid = threadIdx.x;
    const int wq = tid>>5, lane = tid&31;
    const int g = lane>>2, tg = lane&3;
    const int bh = blockIdx.y;
    const int b = bh>>4, h = bh&15;
    const int qb = blockIdx.x*64;

    const __half* kbase = g_k + ((size_t)bh<<10)*DKH;
    const __half* vbase = g_v + ((size_t)bh<<10)*DKH;
    const int*    mbase = mask + (b<<10);
    const uint32_t sKu  = smem_u32(sK);
    const uint32_t sVru = smem_u32(sVr);

    // Q fragments: 4 k16 chunks
    unsigned qf[4][4];
    {
        const __half* q0 = g_q + (((size_t)bh<<10) + qb + wq*16 + g)*DKH;
        const __half* q1 = q0 + 8*DKH;
        #pragma unroll
        for (int c=0;c<4;c++){
            qf[c][0] = *(const unsigned*)(q0 + c*16 + 2*tg);
            qf[c][1] = *(const unsigned*)(q1 + c*16 + 2*tg);
            qf[c][2] = *(const unsigned*)(q0 + c*16 + 2*tg + 8);
            qf[c][3] = *(const unsigned*)(q1 + c*16 + 2*tg + 8);
        }
    }
    // prologue: K0,V0 — 64 rows x 8 segs of 8 halves = 512 cp.asyncs each
    #pragma unroll
    for (int i=0;i<4;i++){
        int idx = i*128 + tid;
        int r = idx>>3, seg = idx&7;
        cpa16(sKu  + (uint32_t)(r*(AT_H*2) + seg*16), kbase + (size_t)r*DKH + seg*8);
        cpa16(sVru + (uint32_t)(r*(AT_H*2) + seg*16), vbase + (size_t)r*DKH + seg*8);
    }
    asm volatile("cp.async.commit_group;" ::: "memory");
    if (tid < 64) sM[0][tid] = mbase[tid];
    asm volatile("cp.async.wait_group 0;" ::: "memory");
    __syncthreads();

    float oA[8][4];
    #pragma unroll
    for (int nb=0;nb<8;nb++){ oA[nb][0]=0.f; oA[nb][1]=0.f; oA[nb][2]=0.f; oA[nb][3]=0.f; }
    float mr0 = -1e30f, mr1 = -1e30f, l0 = 0.f, l1 = 0.f;
    __half* sPw = sP + wq*16*AT_H;

    for (int kt=0;kt<16;kt++){
        const int st = kt & 1;
        if (kt < 15){
            const __half* kn = kbase + (size_t)(kt+1)*64*DKH;
            const __half* vn = vbase + (size_t)(kt+1)*64*DKH;
            uint32_t dK = sKu  + (uint32_t)(st^1)*AT_TILEH*2u;
            uint32_t dV = sVru + (uint32_t)(st^1)*AT_TILEH*2u;
            #pragma unroll
            for (int i=0;i<4;i++){
                int idx = i*128 + tid;
                int r = idx>>3, seg = idx&7;
                cpa16(dK + (uint32_t)(r*(AT_H*2) + seg*16), kn + (size_t)r*DKH + seg*8);
                cpa16(dV + (uint32_t)(r*(AT_H*2) + seg*16), vn + (size_t)r*DKH + seg*8);
            }
            asm volatile("cp.async.commit_group;" ::: "memory");
        }
        // ---- S = Q K^T ----
        float s[8][4];
        #pragma unroll
        for (int nb=0;nb<8;nb++){ s[nb][0]=0.f; s[nb][1]=0.f; s[nb][2]=0.f; s[nb][3]=0.f; }
        const __half* sKs = sK + st*AT_TILEH;
        #pragma unroll
        for (int c=0;c<4;c++){
            unsigned bfr[8][2];
            #pragma unroll
            for (int nb=0;nb<8;nb++){
                const __half* kr = sKs + (nb*8+g)*AT_H + c*16 + 2*tg;
                bfr[nb][0] = *(const unsigned*)(kr);
                bfr[nb][1] = *(const unsigned*)(kr + 8);
            }
            #pragma unroll
            for (int nb=0;nb<8;nb++) mma16(s[nb], qf[c], bfr[nb]);
        }
        // ---- mask + online softmax ----
        float rmax0 = -1e30f, rmax1 = -1e30f;
        #pragma unroll
        for (int nb=0;nb<8;nb++){
            int c0 = nb*8 + 2*tg;
            if (sM[st][c0  ]){ s[nb][0] = -1e30f; s[nb][2] = -1e30f; }
            if (sM[st][c0+1]){ s[nb][1] = -1e30f; s[nb][3] = -1e30f; }
            rmax0 = fmaxf(rmax0, fmaxf(s[nb][0], s[nb][1]));
            rmax1 = fmaxf(rmax1, fmaxf(s[nb][2], s[nb][3]));
        }
        rmax0 = fmaxf(rmax0, __shfl_xor_sync(0xffffffffu, rmax0, 1));
        rmax0 = fmaxf(rmax0, __shfl_xor_sync(0xffffffffu, rmax0, 2));
        rmax1 = fmaxf(rmax1, __shfl_xor_sync(0xffffffffu, rmax1, 1));
        rmax1 = fmaxf(rmax1, __shfl_xor_sync(0xffffffffu, rmax1, 2));
        float nm0 = fmaxf(mr0, rmax0), nm1 = fmaxf(mr1, rmax1);
        float corr0 = __expf(mr0 - nm0), corr1 = __expf(mr1 - nm1);
        mr0 = nm0; mr1 = nm1;
        float sum0 = 0.f, sum1 = 0.f;
        #pragma unroll
        for (int nb=0;nb<8;nb++){
            float p0 = __expf(s[nb][0]-nm0), p1 = __expf(s[nb][1]-nm0);
            float p2 = __expf(s[nb][2]-nm1), p3 = __expf(s[nb][3]-nm1);
            sum0 += p0+p1; sum1 += p2+p3;
            *(__half2*)(sPw + (g  )*AT_H + nb*8 + 2*tg) = __floats2half2_rn(p0, p1);
            *(__half2*)(sPw + (g+8)*AT_H + nb*8 + 2*tg) = __floats2half2_rn(p2, p3);
        }
        sum0 += __shfl_xor_sync(0xffffffffu, sum0, 1);
        sum0 += __shfl_xor_sync(0xffffffffu, sum0, 2);
        sum1 += __shfl_xor_sync(0xffffffffu, sum1, 1);
        sum1 += __shfl_xor_sync(0xffffffffu, sum1, 2);
        l0 = l0*corr0 + sum0;
        l1 = l1*corr1 + sum1;
        #pragma unroll
        for (int nb=0;nb<8;nb++){
            oA[nb][0]*=corr0; oA[nb][1]*=corr0; oA[nb][2]*=corr1; oA[nb][3]*=corr1;
        }
        __syncthreads();   // T1: all warps done reading prev sVT + this-tile sK
        // ---- transpose V(st) -> sVT [d][kv] ----
        {
            const __half* vs = sVr + st*AT_TILEH;
            #pragma unroll
            for (int i=0;i<4;i++){
                int idx = i*128 + tid;
                int c8 = idx>>6, r = idx&63;    // c8: 8-col group, r: kv row
                const __half* src = vs + r*AT_H + c8*8;
                #pragma unroll
                for (int j=0;j<8;j++)
                    sVT[(c8*8+j)*AT_H + r] = src[j];
            }
            if (kt < 15 && tid < 64) sM[st^1][tid] = mbase[(kt+1)*64 + tid];
        }
        __syncthreads();   // T2: sVT visible
        // ---- O += P V ----
        #pragma unroll
        for (int c=0;c<4;c++){
            unsigned afr[4], bfr[8][2];
            afr[0] = *(const unsigned*)(sPw + (g  )*AT_H + c*16 + 2*tg);
            afr[1] = *(const unsigned*)(sPw + (g+8)*AT_H + c*16 + 2*tg);
            afr[2] = *(const unsigned*)(sPw + (g  )*AT_H + c*16 + 2*tg + 8);
            afr[3] = *(const unsigned*)(sPw + (g+8)*AT_H + c*16 + 2*tg + 8);
            #pragma unroll
            for (int nb=0;nb<8;nb++){
                const __half* vr = sVT + (nb*8+g)*AT_H + c*16 + 2*tg;
                bfr[nb][0] = *(const unsigned*)(vr);
                bfr[nb][1] = *(const unsigned*)(vr + 8);
            }
            #pragma unroll
            for (int nb=0;nb<8;nb++) mma16(oA[nb], afr, bfr[nb]);
        }
        asm volatile("cp.async.wait_group 0;" ::: "memory");
        __syncthreads();   // T3: next-stage K/V visible
    }
    // ---- output (fp16 ctx) ----
    float inv0 = 1.f/l0, inv1 = 1.f/l1;
    int s0 = qb + wq*16 + g;
    __half* out0 = g_ctx + (((size_t)(b<<10)) + s0)*DMODEL + h*DKH;
    __half* out1 = out0 + 8*DMODEL;
    #pragma unroll
    for (int nb=0;nb<8;nb++){
        int c0 = nb*8 + 2*tg;
        *(__half2*)(out0 + c0) = __floats2half2_rn(oA[nb][0]*inv0, oA[nb][1]*inv0);
        *(__half2*)(out1 + c0) = __floats2half2_rn(oA[nb][2]*inv1, oA[nb][3]*inv1);
    }
}

// ---------------- launch ----------------
extern "C" void kernel_launch(void* const* d_in, const int* in_sizes, int n_in,
                              void* d_out, int out_size){
    const float* x    = (const float*)d_in[0];
    const int*   mask = (const int*)  d_in[1];
    const float* Wq   = (const float*)d_in[2];
    const float* Wk   = (const float*)d_in[3];
    const float* Wv   = (const float*)d_in[4];
    const float* Wo   = (const float*)d_in[5];
    const float* ln1g = (const float*)d_in[6];
    const float* ln1b = (const float*)d_in[7];
    const float* ln2g = (const float*)d_in[8];
    const float* ln2b = (const float*)d_in[9];
    const float* c1w  = (const float*)d_in[10];
    const float* c1b  = (const float*)d_in[11];
    const float* c2w  = (const float*)d_in[12];
    const float* c2b  = (const float*)d_in[13];
    float* out = (float*)d_out;

    __half *xn, *q, *k, *v, *ctx, *xn2, *h1, *wqkvT, *woT, *c1T, *c2T;
    float *x1;
    cudaGetSymbolAddress((void**)&xn,   g_xn);
    cudaGetSymbolAddress((void**)&q,    g_q);
    cudaGetSymbolAddress((void**)&k,    g_k);
    cudaGetSymbolAddress((void**)&v,    g_v);
    cudaGetSymbolAddress((void**)&ctx,  g_ctx);
    cudaGetSymbolAddress((void**)&x1,   g_x1);
    cudaGetSymbolAddress((void**)&xn2,  g_xn2);
    cudaGetSymbolAddress((void**)&h1,   g_h1);
    cudaGetSymbolAddress((void**)&wqkvT,g_wqkvT);
    cudaGetSymbolAddress((void**)&woT,  g_woT);
    cudaGetSymbolAddress((void**)&c1T,  g_c1T);
    cudaGetSymbolAddress((void**)&c2T,  g_c2T);

    cudaFuncSetAttribute(gemm_h<0,0,0>,  cudaFuncAttributeMaxDynamicSharedMemorySize, SMEM_GEMM);
    cudaFuncSetAttribute(gemm_h<0,1,0>,  cudaFuncAttributeMaxDynamicSharedMemorySize, SMEM_GEMM);
    cudaFuncSetAttribute(gemm_h<1,2,10>, cudaFuncAttributeMaxDynamicSharedMemorySize, SMEM_GEMM);
    cudaFuncSetAttribute(gemm_h<1,3,12>, cudaFuncAttributeMaxDynamicSharedMemorySize, SMEM_GEMM);
    cudaFuncSetAttribute(attn_tc,        cudaFuncAttributeMaxDynamicSharedMemorySize, AT_SMEM_BYTES);

    // 0) weight prep: transpose + fp16 convert ([K][N] -> [N][K])
    dim3 tb(32,8);
    transpose_h<<<dim3(32,32), tb>>>(Wq, wqkvT,                       DMODEL, DMODEL);
    transpose_h<<<dim3(32,32), tb>>>(Wk, wqkvT + (size_t)1024*DMODEL, DMODEL, DMODEL);
    transpose_h<<<dim3(32,32), tb>>>(Wv, wqkvT + (size_t)2048*DMODEL, DMODEL, DMODEL);
    transpose_h<<<dim3(32,32), tb>>>(Wo, woT, DMODEL, DMODEL);
    transpose_h<<<dim3(FF/32, 3*DMODEL/32), tb>>>(c1w, c1T, 3*DMODEL, FF);
    transpose_h<<<dim3(DMODEL/32, 3*FF/32), tb>>>(c2w, c2T, 3*FF, DMODEL);

    // 1) LN1 (fp16 out)
    ln_kernel<<<ROWS,256>>>(x, ln1g, ln1b, xn);

    // 2) fused QKV projection -> q/k/v fp16 [B,H,S,DK]
    dim3 gqkv(3*DMODEL/BN, ROWS/BM);   // (12, 64)
    gemm_h<0,0,0><<<gqkv,256,SMEM_GEMM>>>(xn, wqkvT, q, nullptr, nullptr,
                                          DMODEL, 3*DMODEL, 0.125f, k, v);

    // 3) attention (fp16 flash)
    dim3 ga(SEQ/64, BATCH*NH);
    attn_tc<<<ga,128,AT_SMEM_BYTES>>>(mask);

    // 4) output projection + residual (fp32 x1)
    dim3 go(DMODEL/BN, ROWS/BM);       // (4, 64)
    gemm_h<0,1,0><<<go,256,SMEM_GEMM>>>(ctx, woT, x1, nullptr, x,
                                        DMODEL, DMODEL, 1.0f, nullptr, nullptr);

    // 5) LN2 (fp16 out)
    ln_kernel<<<ROWS,256>>>(x1, ln2g, ln2b, xn2);

    // 6) conv1 (im2col, CIN=1024) + bias + ReLU -> fp16 h1
    gemm_h<1,2,10><<<dim3(FF/BN, ROWS/BM),256,SMEM_GEMM>>>(xn2, c1T, h1, c1b, nullptr,
                                        3*DMODEL, FF, 1.0f, nullptr, nullptr);

    // 7) conv2 (im2col, CIN=4096) + bias + ReLU + residual -> fp32 out
    gemm_h<1,3,12><<<dim3(DMODEL/BN, ROWS/BM),256,SMEM_GEMM>>>(h1, c2T, out, c2b, x1,
                                        3*FF, DMODEL, 1.0f, nullptr, nullptr);
}